// round 2
// baseline (speedup 1.0000x reference)
#include <cuda_runtime.h>
#include <cuda_bf16.h>
#include <cstdint>

// ---------------------------------------------------------------------------
// InteractionPPBlock (DimeNet++) — round 2: 3xTF32 tensor-core GEMMs
//   E=200000, T=2000000, H=256, INT=64, BAS=8, NRAD=6, SBF=42, NB=1, NA=2
// ---------------------------------------------------------------------------

#define H 256
#define INTC 64
#define SBF_DIM 42
#define NRAD 6
#define BAS 8

#define MAXE 200704
#define MAXE_H ((size_t)MAXE * H)
#define MAXE_I ((size_t)MAXE * INTC)

__device__ float g_buf0[MAXE_H];
__device__ float g_buf1[MAXE_H];
__device__ float g_buf2[MAXE_H];
__device__ float g_down[MAXE_I];
__device__ float g_agg[MAXE_I];
__device__ float g_Wr[NRAD * H];

__device__ __forceinline__ float silu(float v) {
    return v / (1.0f + __expf(-v));
}

// split fp32 into tf32 hi + tf32 lo (3xTF32 decomposition)
__device__ __forceinline__ void tf32_split(float v, uint32_t& hi, uint32_t& lo) {
    uint32_t h;
    asm("cvt.rna.tf32.f32 %0, %1;" : "=r"(h) : "f"(v));
    float r = v - __uint_as_float(h);
    uint32_t l;
    asm("cvt.rna.tf32.f32 %0, %1;" : "=r"(l) : "f"(r));
    hi = h; lo = l;
}

__device__ __forceinline__ void mma_tf32(float* d, const uint32_t* a, const uint32_t* b) {
    asm volatile(
        "mma.sync.aligned.m16n8k8.row.col.f32.tf32.tf32.f32 "
        "{%0,%1,%2,%3},{%4,%5,%6,%7},{%8,%9},{%0,%1,%2,%3};\n"
        : "+f"(d[0]), "+f"(d[1]), "+f"(d[2]), "+f"(d[3])
        : "r"(a[0]), "r"(a[1]), "r"(a[2]), "r"(a[3]), "r"(b[0]), "r"(b[1]));
}

// ---------------------------------------------------------------------------
// Tiny: Wr = W_rbf1[6,8] @ W_rbf2[8,256]
// ---------------------------------------------------------------------------
__global__ void wr_kernel(const float* __restrict__ W1, const float* __restrict__ W2) {
    int c = threadIdx.x;
    #pragma unroll
    for (int k = 0; k < NRAD; k++) {
        float v = 0.f;
        #pragma unroll
        for (int j = 0; j < BAS; j++) v += W1[k * BAS + j] * W2[j * H + c];
        g_Wr[k * H + c] = v;
    }
}

// ---------------------------------------------------------------------------
// rbf_e[e,c] = sum_k rbf[e,k] * Wr[k,c]
// ---------------------------------------------------------------------------
__global__ void __launch_bounds__(256) rbfe_kernel(
    const float* __restrict__ rbf, float* __restrict__ out, int E) {
    __shared__ float srbf[64 * NRAD];
    const int tid = threadIdx.x;
    const int e0 = blockIdx.x * 64;
    float w[NRAD];
    #pragma unroll
    for (int k = 0; k < NRAD; k++) w[k] = g_Wr[k * H + tid];
    for (int i = tid; i < 64 * NRAD; i += 256) {
        int e = e0 + i / NRAD;
        srbf[i] = (e < E) ? rbf[(size_t)e * NRAD + (i % NRAD)] : 0.f;
    }
    __syncthreads();
    for (int r = 0; r < 64; r++) {
        int e = e0 + r;
        if (e >= E) break;
        float v = 0.f;
        #pragma unroll
        for (int k = 0; k < NRAD; k++) v += w[k] * srbf[r * NRAD + k];
        out[(size_t)e * H + tid] = v;
    }
}

// ---------------------------------------------------------------------------
// 3xTF32 tensor GEMM: C = epi(A[M,K] @ W[K,N])
//   BM=BN=128, BK=16, 256 threads (8 warps, 2x4), warp tile 64x32
//   epi: (+bias[col]) -> silu -> (*mul) -> (+add)
// ---------------------------------------------------------------------------
#define BM 128
#define BN 128
#define BK 16
#define A_STRIDE (BK + 4)    // 20 words: conflict-free fragment reads
#define B_STRIDE (BN + 8)    // 136 words

__global__ void __launch_bounds__(256) gemm3xtf32(
    const float* __restrict__ A, const float* __restrict__ W,
    const float* __restrict__ bias, const float* __restrict__ mul,
    const float* __restrict__ add, float* __restrict__ C,
    int M, int N, int K) {

    __shared__ uint32_t AsHi[BM][A_STRIDE];
    __shared__ uint32_t AsLo[BM][A_STRIDE];
    __shared__ uint32_t BsHi[BK][B_STRIDE];
    __shared__ uint32_t BsLo[BK][B_STRIDE];

    const int tid  = threadIdx.x;
    const int warp = tid >> 5;
    const int lane = tid & 31;
    const int g    = lane >> 2;   // 0..7
    const int t    = lane & 3;    // 0..3
    const int wm   = warp & 1;    // 0..1 (M dir)
    const int wn   = warp >> 1;   // 0..3 (N dir)

    const int rowBase = blockIdx.x * BM;
    const int colBase = blockIdx.y * BN;

    float acc[4][4][4];
    #pragma unroll
    for (int i = 0; i < 4; i++)
        #pragma unroll
        for (int j = 0; j < 4; j++)
            #pragma unroll
            for (int r = 0; r < 4; r++) acc[i][j][r] = 0.f;

    // global staging indices
    const int a_row = tid >> 1;          // 0..127
    const int a_col = (tid & 1) * 8;     // 0 / 8
    const int b_row = tid >> 4;          // 0..15
    const int b_col = (tid & 15) * 8;    // 0..120

    const int  gArow  = rowBase + a_row;
    const bool aValid = gArow < M;
    const bool bV0    = (colBase + b_col) < N;      // N is a multiple of 64
    const bool bV1    = (colBase + b_col + 4) < N;

    const float* Abase = A + (size_t)gArow * K + a_col;
    const float* Wbase = W + (size_t)b_row * N + colBase + b_col;

    float4 pa0, pa1, pb0, pb1;
    {
        pa0 = make_float4(0.f, 0.f, 0.f, 0.f); pa1 = pa0; pb0 = pa0; pb1 = pa0;
        if (aValid) {
            pa0 = *reinterpret_cast<const float4*>(Abase);
            pa1 = *reinterpret_cast<const float4*>(Abase + 4);
        }
        if (bV0) pb0 = *reinterpret_cast<const float4*>(Wbase);
        if (bV1) pb1 = *reinterpret_cast<const float4*>(Wbase + 4);
    }

    for (int k0 = 0; k0 < K; k0 += BK) {
        // store staged tile into smem, splitting to tf32 hi/lo
        {
            const float av[8] = {pa0.x, pa0.y, pa0.z, pa0.w, pa1.x, pa1.y, pa1.z, pa1.w};
            #pragma unroll
            for (int j = 0; j < 8; j++) {
                uint32_t hi, lo; tf32_split(av[j], hi, lo);
                AsHi[a_row][a_col + j] = hi;
                AsLo[a_row][a_col + j] = lo;
            }
            const float bv[8] = {pb0.x, pb0.y, pb0.z, pb0.w, pb1.x, pb1.y, pb1.z, pb1.w};
            #pragma unroll
            for (int j = 0; j < 8; j++) {
                uint32_t hi, lo; tf32_split(bv[j], hi, lo);
                BsHi[b_row][b_col + j] = hi;
                BsLo[b_row][b_col + j] = lo;
            }
        }
        __syncthreads();

        // prefetch next K-tile
        const int kn = k0 + BK;
        if (kn < K) {
            if (aValid) {
                pa0 = *reinterpret_cast<const float4*>(Abase + kn);
                pa1 = *reinterpret_cast<const float4*>(Abase + kn + 4);
            }
            if (bV0) pb0 = *reinterpret_cast<const float4*>(Wbase + (size_t)kn * N);
            if (bV1) pb1 = *reinterpret_cast<const float4*>(Wbase + (size_t)kn * N + 4);
        }

        // two k8-steps of mma
        #pragma unroll
        for (int ks = 0; ks < 2; ks++) {
            const int kb = ks * 8;
            uint32_t bhi[4][2], blo[4][2];
            #pragma unroll
            for (int nt = 0; nt < 4; nt++) {
                const int n = wn * 32 + nt * 8 + g;
                bhi[nt][0] = BsHi[kb + t][n];
                bhi[nt][1] = BsHi[kb + t + 4][n];
                blo[nt][0] = BsLo[kb + t][n];
                blo[nt][1] = BsLo[kb + t + 4][n];
            }
            #pragma unroll
            for (int mt = 0; mt < 4; mt++) {
                const int m = wm * 64 + mt * 16 + g;
                uint32_t ah[4], al[4];
                ah[0] = AsHi[m][kb + t];     ah[1] = AsHi[m + 8][kb + t];
                ah[2] = AsHi[m][kb + t + 4]; ah[3] = AsHi[m + 8][kb + t + 4];
                al[0] = AsLo[m][kb + t];     al[1] = AsLo[m + 8][kb + t];
                al[2] = AsLo[m][kb + t + 4]; al[3] = AsLo[m + 8][kb + t + 4];
                #pragma unroll
                for (int nt = 0; nt < 4; nt++) {
                    mma_tf32(acc[mt][nt], al, bhi[nt]);   // lo*hi
                    mma_tf32(acc[mt][nt], ah, blo[nt]);   // hi*lo
                    mma_tf32(acc[mt][nt], ah, bhi[nt]);   // hi*hi
                }
            }
        }
        __syncthreads();
    }

    // epilogue
    #pragma unroll
    for (int mt = 0; mt < 4; mt++) {
        const int r0 = rowBase + wm * 64 + mt * 16 + g;
        #pragma unroll
        for (int nt = 0; nt < 4; nt++) {
            const int c0 = colBase + wn * 32 + nt * 8 + 2 * t;
            #pragma unroll
            for (int half = 0; half < 2; half++) {
                const int row = r0 + 8 * half;
                if (row >= M) continue;
                #pragma unroll
                for (int e = 0; e < 2; e++) {
                    const int col = c0 + e;
                    if (col >= N) continue;
                    float v = acc[mt][nt][half * 2 + e];
                    if (bias) v += bias[col];
                    v = silu(v);
                    const size_t idx = (size_t)row * N + col;
                    if (mul) v *= mul[idx];
                    if (add) v += add[idx];
                    C[idx] = v;
                }
            }
        }
    }
}

// ---------------------------------------------------------------------------
// Triplet scatter:  agg[idx_ji] += (sbf @ W_sbf1 @ W_sbf2) * down[idx_kj]
// ---------------------------------------------------------------------------
#define SC_TPB 8
__global__ void __launch_bounds__(512) scatter_kernel(
    const float* __restrict__ sbf, const int* __restrict__ idx_kj,
    const int* __restrict__ idx_ji, const float* __restrict__ W1,
    const float* __restrict__ W2, int T) {
    __shared__ float W1s[SBF_DIM * BAS];
    __shared__ float W2s[BAS * INTC];
    __shared__ float sbfs[SC_TPB][SBF_DIM];
    __shared__ float bs[SC_TPB][BAS];

    const int tid = threadIdx.x;
    for (int i = tid; i < SBF_DIM * BAS; i += 512) W1s[i] = W1[i];
    for (int i = tid; i < BAS * INTC; i += 512) W2s[i] = W2[i];

    const int t = tid >> 6;
    const int c = tid & 63;
    const long tri = (long)blockIdx.x * SC_TPB + t;
    const bool valid = tri < (long)T;

    if (valid && c < SBF_DIM) sbfs[t][c] = sbf[tri * SBF_DIM + c];
    __syncthreads();

    if (valid && c < BAS) {
        float b = 0.f;
        #pragma unroll
        for (int j = 0; j < SBF_DIM; j++) b += sbfs[t][j] * W1s[j * BAS + c];
        bs[t][c] = b;
    }
    __syncthreads();

    if (valid) {
        float s = 0.f;
        #pragma unroll
        for (int k = 0; k < BAS; k++) s += bs[t][k] * W2s[k * INTC + c];
        const int kj = idx_kj[tri];
        const int ji = idx_ji[tri];
        const float m = s * g_down[(size_t)kj * INTC + c];
        atomicAdd(&g_agg[(size_t)ji * INTC + c], m);
    }
}

// ---------------------------------------------------------------------------
// Host orchestration
// ---------------------------------------------------------------------------
static inline void launch_gemm(const float* A, const float* W, const float* bias,
                               const float* mul, const float* add, float* C,
                               int M, int N, int K) {
    dim3 grid((M + BM - 1) / BM, (N + BN - 1) / BN);
    gemm3xtf32<<<grid, 256>>>(A, W, bias, mul, add, C, M, N, K);
}

extern "C" void kernel_launch(void* const* d_in, const int* in_sizes, int n_in,
                              void* d_out, int out_size) {
    const float* x      = (const float*)d_in[0];
    const float* rbf    = (const float*)d_in[1];
    const float* sbf    = (const float*)d_in[2];
    const int*   idx_kj = (const int*)d_in[3];
    const int*   idx_ji = (const int*)d_in[4];
    const float* W_rbf1 = (const float*)d_in[5];
    const float* W_rbf2 = (const float*)d_in[6];
    const float* W_sbf1 = (const float*)d_in[7];
    const float* W_sbf2 = (const float*)d_in[8];
    const float* W_kj   = (const float*)d_in[9];
    const float* b_kj   = (const float*)d_in[10];
    const float* W_ji   = (const float*)d_in[11];
    const float* b_ji   = (const float*)d_in[12];
    const float* W_down = (const float*)d_in[13];
    const float* W_up   = (const float*)d_in[14];
    const float* rb_W1  = (const float*)d_in[15];
    const float* rb_b1  = (const float*)d_in[16];
    const float* rb_W2  = (const float*)d_in[17];
    const float* rb_b2  = (const float*)d_in[18];
    const float* W_lin  = (const float*)d_in[19];
    const float* b_lin  = (const float*)d_in[20];
    const float* ra_W1  = (const float*)d_in[21];
    const float* ra_b1  = (const float*)d_in[22];
    const float* ra_W2  = (const float*)d_in[23];
    const float* ra_b2  = (const float*)d_in[24];

    const int E = in_sizes[0] / H;
    const int T = in_sizes[3];
    float* out = (float*)d_out;

    float *buf0, *buf1, *buf2, *down, *agg;
    cudaGetSymbolAddress((void**)&buf0, g_buf0);
    cudaGetSymbolAddress((void**)&buf1, g_buf1);
    cudaGetSymbolAddress((void**)&buf2, g_buf2);
    cudaGetSymbolAddress((void**)&down, g_down);
    cudaGetSymbolAddress((void**)&agg,  g_agg);

    wr_kernel<<<1, 256>>>(W_rbf1, W_rbf2);
    rbfe_kernel<<<(E + 63) / 64, 256>>>(rbf, buf1, E);                 // buf1 = rbf_e

    launch_gemm(x, W_ji, b_ji, nullptr, nullptr, buf0, E, H, H);       // buf0 = x_ji
    launch_gemm(x, W_kj, b_kj, buf1, nullptr, buf2, E, H, H);          // buf2 = t
    launch_gemm(buf2, W_down, nullptr, nullptr, nullptr, down, E, INTC, H);

    cudaMemsetAsync(agg, 0, (size_t)E * INTC * sizeof(float));
    scatter_kernel<<<(T + SC_TPB - 1) / SC_TPB, 512>>>(sbf, idx_kj, idx_ji,
                                                       W_sbf1, W_sbf2, T);

    launch_gemm(agg, W_up, nullptr, nullptr, buf0, buf2, E, H, INTC);  // buf2 = h0
    launch_gemm(buf2, rb_W1, rb_b1, nullptr, nullptr, buf1, E, H, H);
    launch_gemm(buf1, rb_W2, rb_b2, nullptr, buf2, buf0, E, H, H);     // buf0 = h1
    launch_gemm(buf0, W_lin, b_lin, nullptr, x, buf2, E, H, H);        // buf2 = h2
    launch_gemm(buf2, ra_W1, ra_b1, nullptr, nullptr, buf1, E, H, H);
    launch_gemm(buf1, ra_W2, ra_b2, nullptr, buf2, buf0, E, H, H);     // buf0 = h3

    const float* ra_W1b = ra_W1 + (size_t)H * H;
    const float* ra_b1b = ra_b1 + H;
    const float* ra_W2b = ra_W2 + (size_t)H * H;
    const float* ra_b2b = ra_b2 + H;
    launch_gemm(buf0, ra_W1b, ra_b1b, nullptr, nullptr, buf1, E, H, H);
    launch_gemm(buf1, ra_W2b, ra_b2b, nullptr, buf0, out, E, H, H);
}

// round 4
// speedup vs baseline: 1.4647x; 1.4647x over previous
#include <cuda_runtime.h>
#include <cuda_bf16.h>
#include <cstdint>

// ---------------------------------------------------------------------------
// InteractionPPBlock (DimeNet++) — round 4: legacy mma.sync 3xTF32,
// cp.async 3-stage pipeline, pre-split weights, 16 warps/CTA
// ---------------------------------------------------------------------------

#define H 256
#define INTC 64
#define SBF_DIM 42
#define NRAD 6
#define BAS 8

#define MAXE 200704
#define MAXE_H ((size_t)MAXE * H)
#define MAXE_I ((size_t)MAXE * INTC)

__device__ float g_buf0[MAXE_H];
__device__ float g_buf1[MAXE_H];
__device__ float g_buf2[MAXE_H];
__device__ float g_down[MAXE_I];
__device__ float g_agg[MAXE_I];
__device__ float g_Wr[NRAD * H];
__device__ float g_Wsp[22 * 65536];   // split weights: slot 2w=hi, 2w+1=lo

__device__ __forceinline__ float silu(float v) {
    return v / (1.0f + __expf(-v));
}

__device__ __forceinline__ void tf32_split(float v, uint32_t& hi, uint32_t& lo) {
    uint32_t h;
    asm("cvt.rna.tf32.f32 %0, %1;" : "=r"(h) : "f"(v));
    float r = v - __uint_as_float(h);
    uint32_t l;
    asm("cvt.rna.tf32.f32 %0, %1;" : "=r"(l) : "f"(r));
    hi = h; lo = l;
}

__device__ __forceinline__ void mma_tf32(float* d, const uint32_t* a, const uint32_t* b) {
    asm volatile(
        "mma.sync.aligned.m16n8k8.row.col.f32.tf32.tf32.f32 "
        "{%0,%1,%2,%3},{%4,%5,%6,%7},{%8,%9},{%0,%1,%2,%3};\n"
        : "+f"(d[0]), "+f"(d[1]), "+f"(d[2]), "+f"(d[3])
        : "r"(a[0]), "r"(a[1]), "r"(a[2]), "r"(a[3]), "r"(b[0]), "r"(b[1]));
}

__device__ __forceinline__ uint32_t smem_u32(const void* p) {
    uint32_t a;
    asm("{ .reg .u64 t; cvta.to.shared.u64 t, %1; cvt.u32.u64 %0, t; }" : "=r"(a) : "l"(p));
    return a;
}
__device__ __forceinline__ void cp_async16(uint32_t dst, const void* src, int szr) {
    asm volatile("cp.async.cg.shared.global [%0], [%1], 16, %2;"
                 :: "r"(dst), "l"(src), "r"(szr) : "memory");
}
#define CP_COMMIT() asm volatile("cp.async.commit_group;" ::: "memory")
#define CP_WAIT(n)  asm volatile("cp.async.wait_group %0;" :: "n"(n) : "memory")

// ---------------------------------------------------------------------------
// GEMM: C = epi(A[M,K] @ W[K,N]); W pre-split into Whi/Wlo [K,N]
//   BM=BN=128, BK=16, 512 threads (16 warps, 4x4), warp tile 32x32
// ---------------------------------------------------------------------------
#define BM 128
#define BN 128
#define BK 16
#define STAGES 3
#define ASTR 20                 // A smem row stride (words), conflict-free
#define BSTR 136                // B smem row stride (words), conflict-free
#define A_ST (BM * ASTR)        // 2560 words per stage
#define B_ST (BK * BSTR)        // 2176 words per stage
#define AOFF (STAGES * A_ST)    // 7680
#define BOFF (AOFF + STAGES * B_ST)
#define SMEM_WORDS (BOFF + STAGES * B_ST)
#define SMEM_BYTES (SMEM_WORDS * 4)   // 82944

__device__ __forceinline__ void issue_tile(
    uint32_t s0, const float* __restrict__ A, const float* __restrict__ Whi,
    const float* __restrict__ Wlo, int rowBase, int colBase,
    int M, int N, int K, int kt, int s, int tid) {
    const int k0 = kt * BK;
    // A: 128 rows x 4 col-groups (one 16B per thread)
    {
        const int ar = tid >> 2, ac = (tid & 3) * 4;
        const int gr = rowBase + ar;
        const bool v = gr < M;
        const float* src = A + (size_t)(v ? gr : 0) * K + k0 + ac;
        cp_async16(s0 + (uint32_t)(s * A_ST + ar * ASTR + ac) * 4u, src, v ? 16 : 0);
    }
    // B hi/lo: 16 rows x 32 col-groups
    {
        const int br = tid >> 5, bc = (tid & 31) * 4;
        const int gc = colBase + bc;
        const bool v = gc < N;
        const size_t off = (size_t)(k0 + br) * N + (v ? gc : 0);
        cp_async16(s0 + (uint32_t)(AOFF + s * B_ST + br * BSTR + bc) * 4u, Whi + off, v ? 16 : 0);
        cp_async16(s0 + (uint32_t)(BOFF + s * B_ST + br * BSTR + bc) * 4u, Wlo + off, v ? 16 : 0);
    }
}

__global__ void __launch_bounds__(512, 1) gemm_mma(
    const float* __restrict__ A, const float* __restrict__ Whi,
    const float* __restrict__ Wlo, const float* __restrict__ bias,
    const float* __restrict__ mul, const float* __restrict__ add,
    float* __restrict__ C, int M, int N, int K) {

    extern __shared__ float sm[];
    const uint32_t s0 = smem_u32(sm);

    const int tid  = threadIdx.x;
    const int wid  = tid >> 5;
    const int lane = tid & 31;
    const int g    = lane >> 2;
    const int t    = lane & 3;
    const int wy   = wid >> 2;   // 0..3 (row dir)
    const int wx   = wid & 3;    // 0..3 (col dir)

    const int rowBase = blockIdx.x * BM;
    const int colBase = blockIdx.y * BN;

    float acc[2][4][4];
    #pragma unroll
    for (int i = 0; i < 2; i++)
        #pragma unroll
        for (int j = 0; j < 4; j++)
            #pragma unroll
            for (int r = 0; r < 4; r++) acc[i][j][r] = 0.f;

    const int nk = K / BK;
    #pragma unroll
    for (int s = 0; s < STAGES; s++) {
        if (s < nk) issue_tile(s0, A, Whi, Wlo, rowBase, colBase, M, N, K, s, s, tid);
        CP_COMMIT();
    }

    for (int it = 0; it < nk; ++it) {
        const int pend = nk - 1 - it;   // committed groups newer than tile `it`
        if (pend >= 2)      CP_WAIT(2);
        else if (pend == 1) CP_WAIT(1);
        else                CP_WAIT(0);
        __syncthreads();

        const int s = it % STAGES;
        const float* As = sm + s * A_ST;
        const float* Bh = sm + AOFF + s * B_ST;
        const float* Bl = sm + BOFF + s * B_ST;

        #pragma unroll
        for (int ks = 0; ks < 2; ks++) {
            const int kb = ks * 8;
            uint32_t bh[4][2], bl[4][2];
            #pragma unroll
            for (int nt = 0; nt < 4; nt++) {
                const int n = wx * 32 + nt * 8 + g;
                bh[nt][0] = __float_as_uint(Bh[(kb + t) * BSTR + n]);
                bh[nt][1] = __float_as_uint(Bh[(kb + t + 4) * BSTR + n]);
                bl[nt][0] = __float_as_uint(Bl[(kb + t) * BSTR + n]);
                bl[nt][1] = __float_as_uint(Bl[(kb + t + 4) * BSTR + n]);
            }
            #pragma unroll
            for (int mt = 0; mt < 2; mt++) {
                const int r0 = wy * 32 + mt * 16 + g;
                float raw[4];
                raw[0] = As[r0 * ASTR + kb + t];
                raw[1] = As[(r0 + 8) * ASTR + kb + t];
                raw[2] = As[r0 * ASTR + kb + t + 4];
                raw[3] = As[(r0 + 8) * ASTR + kb + t + 4];
                uint32_t ah[4], al[4];
                #pragma unroll
                for (int i = 0; i < 4; i++) tf32_split(raw[i], ah[i], al[i]);
                #pragma unroll
                for (int nt = 0; nt < 4; nt++) {
                    mma_tf32(acc[mt][nt], al, bh[nt]);
                    mma_tf32(acc[mt][nt], ah, bl[nt]);
                    mma_tf32(acc[mt][nt], ah, bh[nt]);
                }
            }
        }
        __syncthreads();

        const int nx = it + STAGES;
        if (nx < nk) {
            issue_tile(s0, A, Whi, Wlo, rowBase, colBase, M, N, K, nx, s, tid);
            CP_COMMIT();
        }
    }

    // epilogue: (+bias) -> silu -> (*mul) -> (+add)
    #pragma unroll
    for (int mt = 0; mt < 2; mt++) {
        #pragma unroll
        for (int nt = 0; nt < 4; nt++) {
            const int c0 = colBase + wx * 32 + nt * 8 + 2 * t;
            #pragma unroll
            for (int half = 0; half < 2; half++) {
                const int row = rowBase + wy * 32 + mt * 16 + g + 8 * half;
                if (row >= M) continue;
                #pragma unroll
                for (int e = 0; e < 2; e++) {
                    const int col = c0 + e;
                    if (col >= N) continue;
                    float v = acc[mt][nt][half * 2 + e];
                    if (bias) v += bias[col];
                    v = silu(v);
                    const size_t idx = (size_t)row * N + col;
                    if (mul) v *= mul[idx];
                    if (add) v += add[idx];
                    C[idx] = v;
                }
            }
        }
    }
}

// ---------------------------------------------------------------------------
// Prep: split weight into tf32 hi/lo (stored as fp32 bit patterns)
// ---------------------------------------------------------------------------
__global__ void split_kernel(const float* __restrict__ src, float* __restrict__ hi,
                             float* __restrict__ lo, int n) {
    int i = blockIdx.x * 256 + threadIdx.x;
    if (i < n) {
        uint32_t h, l;
        tf32_split(src[i], h, l);
        hi[i] = __uint_as_float(h);
        lo[i] = __uint_as_float(l);
    }
}

// ---------------------------------------------------------------------------
// Tiny basis kernels
// ---------------------------------------------------------------------------
__global__ void wr_kernel(const float* __restrict__ W1, const float* __restrict__ W2) {
    int c = threadIdx.x;
    #pragma unroll
    for (int k = 0; k < NRAD; k++) {
        float v = 0.f;
        #pragma unroll
        for (int j = 0; j < BAS; j++) v += W1[k * BAS + j] * W2[j * H + c];
        g_Wr[k * H + c] = v;
    }
}

__global__ void __launch_bounds__(256) rbfe_kernel(
    const float* __restrict__ rbf, float* __restrict__ out, int E) {
    __shared__ float srbf[64 * NRAD];
    const int tid = threadIdx.x;
    const int e0 = blockIdx.x * 64;
    float w[NRAD];
    #pragma unroll
    for (int k = 0; k < NRAD; k++) w[k] = g_Wr[k * H + tid];
    for (int i = tid; i < 64 * NRAD; i += 256) {
        int e = e0 + i / NRAD;
        srbf[i] = (e < E) ? rbf[(size_t)e * NRAD + (i % NRAD)] : 0.f;
    }
    __syncthreads();
    for (int r = 0; r < 64; r++) {
        int e = e0 + r;
        if (e >= E) break;
        float v = 0.f;
        #pragma unroll
        for (int k = 0; k < NRAD; k++) v += w[k] * srbf[r * NRAD + k];
        out[(size_t)e * H + tid] = v;
    }
}

// ---------------------------------------------------------------------------
// Triplet scatter
// ---------------------------------------------------------------------------
#define SC_TPB 8
__global__ void __launch_bounds__(512) scatter_kernel(
    const float* __restrict__ sbf, const int* __restrict__ idx_kj,
    const int* __restrict__ idx_ji, const float* __restrict__ W1,
    const float* __restrict__ W2, int T) {
    __shared__ float W1s[SBF_DIM * BAS];
    __shared__ float W2s[BAS * INTC];
    __shared__ float sbfs[SC_TPB][SBF_DIM];
    __shared__ float bs[SC_TPB][BAS];

    const int tid = threadIdx.x;
    for (int i = tid; i < SBF_DIM * BAS; i += 512) W1s[i] = W1[i];
    for (int i = tid; i < BAS * INTC; i += 512) W2s[i] = W2[i];

    const int t = tid >> 6;
    const int c = tid & 63;
    const long tri = (long)blockIdx.x * SC_TPB + t;
    const bool valid = tri < (long)T;

    if (valid && c < SBF_DIM) sbfs[t][c] = sbf[tri * SBF_DIM + c];
    __syncthreads();

    if (valid && c < BAS) {
        float b = 0.f;
        #pragma unroll
        for (int j = 0; j < SBF_DIM; j++) b += sbfs[t][j] * W1s[j * BAS + c];
        bs[t][c] = b;
    }
    __syncthreads();

    if (valid) {
        float s = 0.f;
        #pragma unroll
        for (int k = 0; k < BAS; k++) s += bs[t][k] * W2s[k * INTC + c];
        const int kj = idx_kj[tri];
        const int ji = idx_ji[tri];
        const float m = s * g_down[(size_t)kj * INTC + c];
        atomicAdd(&g_agg[(size_t)ji * INTC + c], m);
    }
}

// ---------------------------------------------------------------------------
// Host orchestration
// ---------------------------------------------------------------------------
static inline void launch_gemm(const float* A, const float* whi, const float* wlo,
                               const float* bias, const float* mul, const float* add,
                               float* C, int M, int N, int K) {
    dim3 grid((M + BM - 1) / BM, (N + BN - 1) / BN);
    gemm_mma<<<grid, 512, SMEM_BYTES>>>(A, whi, wlo, bias, mul, add, C, M, N, K);
}

extern "C" void kernel_launch(void* const* d_in, const int* in_sizes, int n_in,
                              void* d_out, int out_size) {
    const float* x      = (const float*)d_in[0];
    const float* rbf    = (const float*)d_in[1];
    const float* sbf    = (const float*)d_in[2];
    const int*   idx_kj = (const int*)d_in[3];
    const int*   idx_ji = (const int*)d_in[4];
    const float* W_rbf1 = (const float*)d_in[5];
    const float* W_rbf2 = (const float*)d_in[6];
    const float* W_sbf1 = (const float*)d_in[7];
    const float* W_sbf2 = (const float*)d_in[8];
    const float* W_kj   = (const float*)d_in[9];
    const float* b_kj   = (const float*)d_in[10];
    const float* W_ji   = (const float*)d_in[11];
    const float* b_ji   = (const float*)d_in[12];
    const float* W_down = (const float*)d_in[13];
    const float* W_up   = (const float*)d_in[14];
    const float* rb_W1  = (const float*)d_in[15];
    const float* rb_b1  = (const float*)d_in[16];
    const float* rb_W2  = (const float*)d_in[17];
    const float* rb_b2  = (const float*)d_in[18];
    const float* W_lin  = (const float*)d_in[19];
    const float* b_lin  = (const float*)d_in[20];
    const float* ra_W1  = (const float*)d_in[21];
    const float* ra_b1  = (const float*)d_in[22];
    const float* ra_W2  = (const float*)d_in[23];
    const float* ra_b2  = (const float*)d_in[24];

    const int E = in_sizes[0] / H;
    const int T = in_sizes[3];
    float* out = (float*)d_out;

    cudaFuncSetAttribute(gemm_mma, cudaFuncAttributeMaxDynamicSharedMemorySize, SMEM_BYTES);

    float *buf0, *buf1, *buf2, *down, *agg, *wsp;
    cudaGetSymbolAddress((void**)&buf0, g_buf0);
    cudaGetSymbolAddress((void**)&buf1, g_buf1);
    cudaGetSymbolAddress((void**)&buf2, g_buf2);
    cudaGetSymbolAddress((void**)&down, g_down);
    cudaGetSymbolAddress((void**)&agg,  g_agg);
    cudaGetSymbolAddress((void**)&wsp,  g_Wsp);
    #define WHI(w) (wsp + (size_t)(2 * (w)) * 65536)
    #define WLO(w) (wsp + (size_t)(2 * (w) + 1) * 65536)

    // ---- prep: split all weights into tf32 hi/lo ----
    const int g64k = (65536 + 255) / 256, g16k = (16384 + 255) / 256;
    split_kernel<<<g64k, 256>>>(W_ji,  WHI(0), WLO(0), 65536);
    split_kernel<<<g64k, 256>>>(W_kj,  WHI(1), WLO(1), 65536);
    split_kernel<<<g16k, 256>>>(W_down, WHI(2), WLO(2), 16384);
    split_kernel<<<g16k, 256>>>(W_up,  WHI(3), WLO(3), 16384);
    split_kernel<<<g64k, 256>>>(rb_W1, WHI(4), WLO(4), 65536);
    split_kernel<<<g64k, 256>>>(rb_W2, WHI(5), WLO(5), 65536);
    split_kernel<<<g64k, 256>>>(W_lin, WHI(6), WLO(6), 65536);
    split_kernel<<<g64k, 256>>>(ra_W1, WHI(7), WLO(7), 65536);
    split_kernel<<<g64k, 256>>>(ra_W2, WHI(8), WLO(8), 65536);
    split_kernel<<<g64k, 256>>>(ra_W1 + (size_t)H * H, WHI(9),  WLO(9),  65536);
    split_kernel<<<g64k, 256>>>(ra_W2 + (size_t)H * H, WHI(10), WLO(10), 65536);

    wr_kernel<<<1, 256>>>(W_rbf1, W_rbf2);
    rbfe_kernel<<<(E + 63) / 64, 256>>>(rbf, buf1, E);                        // buf1 = rbf_e

    launch_gemm(x, WHI(0), WLO(0), b_ji, nullptr, nullptr, buf0, E, H, H);    // buf0 = x_ji
    launch_gemm(x, WHI(1), WLO(1), b_kj, buf1, nullptr, buf2, E, H, H);       // buf2 = t
    launch_gemm(buf2, WHI(2), WLO(2), nullptr, nullptr, nullptr, down, E, INTC, H);

    cudaMemsetAsync(agg, 0, (size_t)E * INTC * sizeof(float));
    scatter_kernel<<<(T + SC_TPB - 1) / SC_TPB, 512>>>(sbf, idx_kj, idx_ji,
                                                       W_sbf1, W_sbf2, T);

    launch_gemm(agg, WHI(3), WLO(3), nullptr, nullptr, buf0, buf2, E, H, INTC); // h0
    launch_gemm(buf2, WHI(4), WLO(4), rb_b1, nullptr, nullptr, buf1, E, H, H);
    launch_gemm(buf1, WHI(5), WLO(5), rb_b2, nullptr, buf2, buf0, E, H, H);     // h1
    launch_gemm(buf0, WHI(6), WLO(6), b_lin, nullptr, x, buf2, E, H, H);        // h2
    launch_gemm(buf2, WHI(7), WLO(7), ra_b1, nullptr, nullptr, buf1, E, H, H);
    launch_gemm(buf1, WHI(8), WLO(8), ra_b2, nullptr, buf2, buf0, E, H, H);     // h3
    launch_gemm(buf0, WHI(9), WLO(9), ra_b1 + H, nullptr, nullptr, buf1, E, H, H);
    launch_gemm(buf1, WHI(10), WLO(10), ra_b2 + H, nullptr, buf0, out, E, H, H);
}

// round 5
// speedup vs baseline: 1.5607x; 1.0655x over previous
#include <cuda_runtime.h>
#include <cuda_bf16.h>
#include <cstdint>

// ---------------------------------------------------------------------------
// InteractionPPBlock (DimeNet++) — round 5: 3xTF32 mma pipeline (4-stage,
// single-sync), vectorized red.v4 scatter, profiling-friendly launch order
// ---------------------------------------------------------------------------

#define H 256
#define INTC 64
#define SBF_DIM 42
#define NRAD 6
#define BAS 8

#define MAXE 200704
#define MAXE_H ((size_t)MAXE * H)
#define MAXE_I ((size_t)MAXE * INTC)

__device__ float g_buf0[MAXE_H];
__device__ float g_buf1[MAXE_H];
__device__ float g_buf2[MAXE_H];
__device__ float g_down[MAXE_I];
__device__ float g_agg[MAXE_I];
__device__ float g_Wr[NRAD * H];
__device__ float g_Wsp[22 * 65536];   // split weights: slot 2w=hi, 2w+1=lo

__device__ __forceinline__ float silu(float v) {
    return v / (1.0f + __expf(-v));
}

__device__ __forceinline__ void tf32_split(float v, uint32_t& hi, uint32_t& lo) {
    uint32_t h;
    asm("cvt.rna.tf32.f32 %0, %1;" : "=r"(h) : "f"(v));
    float r = v - __uint_as_float(h);
    uint32_t l;
    asm("cvt.rna.tf32.f32 %0, %1;" : "=r"(l) : "f"(r));
    hi = h; lo = l;
}

__device__ __forceinline__ void mma_tf32(float* d, const uint32_t* a, const uint32_t* b) {
    asm volatile(
        "mma.sync.aligned.m16n8k8.row.col.f32.tf32.tf32.f32 "
        "{%0,%1,%2,%3},{%4,%5,%6,%7},{%8,%9},{%0,%1,%2,%3};\n"
        : "+f"(d[0]), "+f"(d[1]), "+f"(d[2]), "+f"(d[3])
        : "r"(a[0]), "r"(a[1]), "r"(a[2]), "r"(a[3]), "r"(b[0]), "r"(b[1]));
}

__device__ __forceinline__ uint32_t smem_u32(const void* p) {
    uint32_t a;
    asm("{ .reg .u64 t; cvta.to.shared.u64 t, %1; cvt.u32.u64 %0, t; }" : "=r"(a) : "l"(p));
    return a;
}
__device__ __forceinline__ void cp_async16(uint32_t dst, const void* src, int szr) {
    asm volatile("cp.async.cg.shared.global [%0], [%1], 16, %2;"
                 :: "r"(dst), "l"(src), "r"(szr) : "memory");
}
#define CP_COMMIT() asm volatile("cp.async.commit_group;" ::: "memory")
#define CP_WAIT(n)  asm volatile("cp.async.wait_group %0;" :: "n"(n) : "memory")

// ---------------------------------------------------------------------------
// GEMM: C = epi(A[M,K] @ W[K,N]); W pre-split into Whi/Wlo [K,N]
//   BM=BN=128, BK=16, 512 threads (16 warps, 4x4), 4 stages, 1 sync/tile
// ---------------------------------------------------------------------------
#define BM 128
#define BN 128
#define BK 16
#define STAGES 4
#define ASTR 20
#define BSTR 136
#define A_ST (BM * ASTR)
#define B_ST (BK * BSTR)
#define AOFF (STAGES * A_ST)
#define BOFF (AOFF + STAGES * B_ST)
#define SMEM_WORDS (BOFF + STAGES * B_ST)
#define SMEM_BYTES (SMEM_WORDS * 4)   // 110592

__device__ __forceinline__ void issue_tile(
    uint32_t s0, const float* __restrict__ A, const float* __restrict__ Whi,
    const float* __restrict__ Wlo, int rowBase, int colBase,
    int M, int N, int K, int kt, int s, int tid) {
    const int k0 = kt * BK;
    {
        const int ar = tid >> 2, ac = (tid & 3) * 4;
        const int gr = rowBase + ar;
        const bool v = gr < M;
        const float* src = A + (size_t)(v ? gr : 0) * K + k0 + ac;
        cp_async16(s0 + (uint32_t)(s * A_ST + ar * ASTR + ac) * 4u, src, v ? 16 : 0);
    }
    {
        const int br = tid >> 5, bc = (tid & 31) * 4;
        const int gc = colBase + bc;
        const bool v = gc < N;
        const size_t off = (size_t)(k0 + br) * N + (v ? gc : 0);
        cp_async16(s0 + (uint32_t)(AOFF + s * B_ST + br * BSTR + bc) * 4u, Whi + off, v ? 16 : 0);
        cp_async16(s0 + (uint32_t)(BOFF + s * B_ST + br * BSTR + bc) * 4u, Wlo + off, v ? 16 : 0);
    }
}

__global__ void __launch_bounds__(512, 1) gemm_mma(
    const float* __restrict__ A, const float* __restrict__ Whi,
    const float* __restrict__ Wlo, const float* __restrict__ bias,
    const float* __restrict__ mul, const float* __restrict__ add,
    float* __restrict__ C, int M, int N, int K) {

    extern __shared__ float sm[];
    const uint32_t s0 = smem_u32(sm);

    const int tid  = threadIdx.x;
    const int wid  = tid >> 5;
    const int lane = tid & 31;
    const int g    = lane >> 2;
    const int t    = lane & 3;
    const int wy   = wid >> 2;
    const int wx   = wid & 3;

    const int rowBase = blockIdx.x * BM;
    const int colBase = blockIdx.y * BN;

    float acc[2][4][4];
    #pragma unroll
    for (int i = 0; i < 2; i++)
        #pragma unroll
        for (int j = 0; j < 4; j++)
            #pragma unroll
            for (int r = 0; r < 4; r++) acc[i][j][r] = 0.f;

    const int nk = K / BK;

    // prologue: STAGES-1 tiles
    #pragma unroll
    for (int s = 0; s < STAGES - 1; s++) {
        if (s < nk) {
            issue_tile(s0, A, Whi, Wlo, rowBase, colBase, M, N, K, s, s, tid);
            CP_COMMIT();
        }
    }

    for (int it = 0; it < nk; ++it) {
        const int pend = nk - 1 - it;
        if (pend >= 2)      CP_WAIT(2);
        else if (pend == 1) CP_WAIT(1);
        else                CP_WAIT(0);
        __syncthreads();   // all warps done with tile it-1; slot (it-1)%STAGES free

        const int nx = it + STAGES - 1;
        if (nx < nk) {
            issue_tile(s0, A, Whi, Wlo, rowBase, colBase, M, N, K, nx, nx % STAGES, tid);
            CP_COMMIT();
        }

        const int s = it % STAGES;
        const float* As = sm + s * A_ST;
        const float* Bh = sm + AOFF + s * B_ST;
        const float* Bl = sm + BOFF + s * B_ST;

        #pragma unroll
        for (int ks = 0; ks < 2; ks++) {
            const int kb = ks * 8;
            uint32_t bh[4][2], bl[4][2];
            #pragma unroll
            for (int nt = 0; nt < 4; nt++) {
                const int n = wx * 32 + nt * 8 + g;
                bh[nt][0] = __float_as_uint(Bh[(kb + t) * BSTR + n]);
                bh[nt][1] = __float_as_uint(Bh[(kb + t + 4) * BSTR + n]);
                bl[nt][0] = __float_as_uint(Bl[(kb + t) * BSTR + n]);
                bl[nt][1] = __float_as_uint(Bl[(kb + t + 4) * BSTR + n]);
            }
            #pragma unroll
            for (int mt = 0; mt < 2; mt++) {
                const int r0 = wy * 32 + mt * 16 + g;
                float raw[4];
                raw[0] = As[r0 * ASTR + kb + t];
                raw[1] = As[(r0 + 8) * ASTR + kb + t];
                raw[2] = As[r0 * ASTR + kb + t + 4];
                raw[3] = As[(r0 + 8) * ASTR + kb + t + 4];
                uint32_t ah[4], al[4];
                #pragma unroll
                for (int i = 0; i < 4; i++) tf32_split(raw[i], ah[i], al[i]);
                #pragma unroll
                for (int nt = 0; nt < 4; nt++) {
                    mma_tf32(acc[mt][nt], al, bh[nt]);
                    mma_tf32(acc[mt][nt], ah, bl[nt]);
                    mma_tf32(acc[mt][nt], ah, bh[nt]);
                }
            }
        }
    }

    // epilogue
    #pragma unroll
    for (int mt = 0; mt < 2; mt++) {
        #pragma unroll
        for (int nt = 0; nt < 4; nt++) {
            const int c0 = colBase + wx * 32 + nt * 8 + 2 * t;
            #pragma unroll
            for (int half = 0; half < 2; half++) {
                const int row = rowBase + wy * 32 + mt * 16 + g + 8 * half;
                if (row >= M) continue;
                #pragma unroll
                for (int e = 0; e < 2; e++) {
                    const int col = c0 + e;
                    if (col >= N) continue;
                    float v = acc[mt][nt][half * 2 + e];
                    if (bias) v += bias[col];
                    v = silu(v);
                    const size_t idx = (size_t)row * N + col;
                    if (mul) v *= mul[idx];
                    if (add) v += add[idx];
                    C[idx] = v;
                }
            }
        }
    }
}

// ---------------------------------------------------------------------------
// Prep: split ALL weights into tf32 hi/lo in ONE launch (blockIdx.y = weight)
// ---------------------------------------------------------------------------
__global__ void split_all_kernel(
    const float* p0, const float* p1, const float* p2, const float* p3,
    const float* p4, const float* p5, const float* p6, const float* p7,
    const float* p8, const float* p9, const float* p10) {
    const float* srcs[11] = {p0, p1, p2, p3, p4, p5, p6, p7, p8, p9, p10};
    const int sizes[11] = {65536, 65536, 16384, 16384, 65536, 65536, 65536,
                           65536, 65536, 65536, 65536};
    const int w = blockIdx.y;
    const int i = blockIdx.x * 256 + threadIdx.x;
    if (i < sizes[w]) {
        uint32_t h, l;
        tf32_split(srcs[w][i], h, l);
        g_Wsp[(size_t)(2 * w) * 65536 + i]     = __uint_as_float(h);
        g_Wsp[(size_t)(2 * w + 1) * 65536 + i] = __uint_as_float(l);
    }
}

__global__ void zero_agg_kernel(int n4) {
    int i = blockIdx.x * 256 + threadIdx.x;
    if (i < n4) reinterpret_cast<float4*>(g_agg)[i] = make_float4(0.f, 0.f, 0.f, 0.f);
}

// ---------------------------------------------------------------------------
// Tiny basis kernels
// ---------------------------------------------------------------------------
__global__ void wr_kernel(const float* __restrict__ W1, const float* __restrict__ W2) {
    int c = threadIdx.x;
    #pragma unroll
    for (int k = 0; k < NRAD; k++) {
        float v = 0.f;
        #pragma unroll
        for (int j = 0; j < BAS; j++) v += W1[k * BAS + j] * W2[j * H + c];
        g_Wr[k * H + c] = v;
    }
}

__global__ void __launch_bounds__(256) rbfe_kernel(
    const float* __restrict__ rbf, float* __restrict__ out, int E) {
    __shared__ float srbf[64 * NRAD];
    const int tid = threadIdx.x;
    const int e0 = blockIdx.x * 64;
    float w[NRAD];
    #pragma unroll
    for (int k = 0; k < NRAD; k++) w[k] = g_Wr[k * H + tid];
    for (int i = tid; i < 64 * NRAD; i += 256) {
        int e = e0 + i / NRAD;
        srbf[i] = (e < E) ? rbf[(size_t)e * NRAD + (i % NRAD)] : 0.f;
    }
    __syncthreads();
    for (int r = 0; r < 64; r++) {
        int e = e0 + r;
        if (e >= E) break;
        float v = 0.f;
        #pragma unroll
        for (int k = 0; k < NRAD; k++) v += w[k] * srbf[r * NRAD + k];
        out[(size_t)e * H + tid] = v;
    }
}

// ---------------------------------------------------------------------------
// Triplet scatter: 16 lanes/triplet, float4 channels, red.global.add.v4.f32
// ---------------------------------------------------------------------------
#define SC_TRI 32
__global__ void __launch_bounds__(512) scatter_v4_kernel(
    const float* __restrict__ sbf, const int* __restrict__ idx_kj,
    const int* __restrict__ idx_ji, const float* __restrict__ W1,
    const float* __restrict__ W2, int T) {
    __shared__ float W1s[SBF_DIM * BAS];
    __shared__ float W2s[BAS * INTC];
    __shared__ float sbfs[SC_TRI][SBF_DIM + 2];
    __shared__ float bs[SC_TRI][BAS];

    const int tid = threadIdx.x;
    for (int i = tid; i < SBF_DIM * BAS; i += 512) W1s[i] = W1[i];
    for (int i = tid; i < BAS * INTC; i += 512) W2s[i] = W2[i];

    const int t = tid >> 4;        // triplet slot 0..31
    const int l = tid & 15;        // lane within triplet
    const long tri = (long)blockIdx.x * SC_TRI + t;
    const bool valid = tri < (long)T;

    if (valid) {
        #pragma unroll
        for (int i = l; i < SBF_DIM; i += 16) sbfs[t][i] = sbf[tri * SBF_DIM + i];
    }
    __syncthreads();

    if (valid && l < BAS) {
        float b = 0.f;
        #pragma unroll
        for (int j = 0; j < SBF_DIM; j++) b += sbfs[t][j] * W1s[j * BAS + l];
        bs[t][l] = b;
    }
    __syncthreads();

    if (valid) {
        const int c0 = l * 4;
        float s0 = 0.f, s1 = 0.f, s2 = 0.f, s3 = 0.f;
        #pragma unroll
        for (int k = 0; k < BAS; k++) {
            const float bk = bs[t][k];
            const float* w = &W2s[k * INTC + c0];
            s0 += bk * w[0]; s1 += bk * w[1]; s2 += bk * w[2]; s3 += bk * w[3];
        }
        const int kj = idx_kj[tri];
        const int ji = idx_ji[tri];
        const float4 d = __ldg(reinterpret_cast<const float4*>(&g_down[(size_t)kj * INTC + c0]));
        s0 *= d.x; s1 *= d.y; s2 *= d.z; s3 *= d.w;
        float* dst = &g_agg[(size_t)ji * INTC + c0];
        asm volatile("red.global.add.v4.f32 [%0], {%1,%2,%3,%4};"
                     :: "l"(dst), "f"(s0), "f"(s1), "f"(s2), "f"(s3) : "memory");
    }
}

// ---------------------------------------------------------------------------
// Host orchestration
// ---------------------------------------------------------------------------
static inline void launch_gemm(const float* A, const float* whi, const float* wlo,
                               const float* bias, const float* mul, const float* add,
                               float* C, int M, int N, int K) {
    dim3 grid((M + BM - 1) / BM, (N + BN - 1) / BN);
    gemm_mma<<<grid, 512, SMEM_BYTES>>>(A, whi, wlo, bias, mul, add, C, M, N, K);
}

extern "C" void kernel_launch(void* const* d_in, const int* in_sizes, int n_in,
                              void* d_out, int out_size) {
    const float* x      = (const float*)d_in[0];
    const float* rbf    = (const float*)d_in[1];
    const float* sbf    = (const float*)d_in[2];
    const int*   idx_kj = (const int*)d_in[3];
    const int*   idx_ji = (const int*)d_in[4];
    const float* W_rbf1 = (const float*)d_in[5];
    const float* W_rbf2 = (const float*)d_in[6];
    const float* W_sbf1 = (const float*)d_in[7];
    const float* W_sbf2 = (const float*)d_in[8];
    const float* W_kj   = (const float*)d_in[9];
    const float* b_kj   = (const float*)d_in[10];
    const float* W_ji   = (const float*)d_in[11];
    const float* b_ji   = (const float*)d_in[12];
    const float* W_down = (const float*)d_in[13];
    const float* W_up   = (const float*)d_in[14];
    const float* rb_W1  = (const float*)d_in[15];
    const float* rb_b1  = (const float*)d_in[16];
    const float* rb_W2  = (const float*)d_in[17];
    const float* rb_b2  = (const float*)d_in[18];
    const float* W_lin  = (const float*)d_in[19];
    const float* b_lin  = (const float*)d_in[20];
    const float* ra_W1  = (const float*)d_in[21];
    const float* ra_b1  = (const float*)d_in[22];
    const float* ra_W2  = (const float*)d_in[23];
    const float* ra_b2  = (const float*)d_in[24];

    const int E = in_sizes[0] / H;
    const int T = in_sizes[3];
    float* out = (float*)d_out;

    cudaFuncSetAttribute(gemm_mma, cudaFuncAttributeMaxDynamicSharedMemorySize, SMEM_BYTES);

    float *buf0, *buf1, *buf2, *down, *agg, *wsp;
    cudaGetSymbolAddress((void**)&buf0, g_buf0);
    cudaGetSymbolAddress((void**)&buf1, g_buf1);
    cudaGetSymbolAddress((void**)&buf2, g_buf2);
    cudaGetSymbolAddress((void**)&down, g_down);
    cudaGetSymbolAddress((void**)&agg,  g_agg);
    cudaGetSymbolAddress((void**)&wsp,  g_Wsp);
    #define WHI(w) (wsp + (size_t)(2 * (w)) * 65536)
    #define WLO(w) (wsp + (size_t)(2 * (w) + 1) * 65536)

    // L1: split all weights
    split_all_kernel<<<dim3(256, 11), 256>>>(
        W_ji, W_kj, W_down, W_up, rb_W1, rb_W2, W_lin, ra_W1, ra_W2,
        ra_W1 + (size_t)H * H, ra_W2 + (size_t)H * H);
    // L2-L4
    wr_kernel<<<1, 256>>>(W_rbf1, W_rbf2);
    zero_agg_kernel<<<(E * INTC / 4 + 255) / 256, 256>>>(E * INTC / 4);
    rbfe_kernel<<<(E + 63) / 64, 256>>>(rbf, buf1, E);                        // buf1 = rbf_e
    // L5: x_ji   L6: x_kj  <- profiled launch (big H x H GEMM)
    launch_gemm(x, WHI(0), WLO(0), b_ji, nullptr, nullptr, buf0, E, H, H);    // buf0 = x_ji
    launch_gemm(x, WHI(1), WLO(1), b_kj, buf1, nullptr, buf2, E, H, H);       // buf2 = t
    launch_gemm(buf2, WHI(2), WLO(2), nullptr, nullptr, nullptr, down, E, INTC, H);

    scatter_v4_kernel<<<(T + SC_TRI - 1) / SC_TRI, 512>>>(sbf, idx_kj, idx_ji,
                                                          W_sbf1, W_sbf2, T);

    launch_gemm(agg, WHI(3), WLO(3), nullptr, nullptr, buf0, buf2, E, H, INTC); // h0
    launch_gemm(buf2, WHI(4), WLO(4), rb_b1, nullptr, nullptr, buf1, E, H, H);
    launch_gemm(buf1, WHI(5), WLO(5), rb_b2, nullptr, buf2, buf0, E, H, H);     // h1
    launch_gemm(buf0, WHI(6), WLO(6), b_lin, nullptr, x, buf2, E, H, H);        // h2
    launch_gemm(buf2, WHI(7), WLO(7), ra_b1, nullptr, nullptr, buf1, E, H, H);
    launch_gemm(buf1, WHI(8), WLO(8), ra_b2, nullptr, buf2, buf0, E, H, H);     // h3
    launch_gemm(buf0, WHI(9), WLO(9), ra_b1 + H, nullptr, nullptr, buf1, E, H, H);
    launch_gemm(buf1, WHI(10), WLO(10), ra_b2 + H, nullptr, buf0, out, E, H, H);
}

// round 6
// speedup vs baseline: 2.0528x; 1.3154x over previous
#include <cuda_runtime.h>
#include <cuda_fp16.h>
#include <cstdint>

// ---------------------------------------------------------------------------
// InteractionPPBlock (DimeNet++) — round 6: 2xFP16-split GEMMs (3-term mma
// m16n8k16), pre-split activations & fragment-permuted weights, cp.async x4
// ---------------------------------------------------------------------------

#define H 256
#define INTC 64
#define SBF_DIM 42
#define NRAD 6
#define BAS 8

#define MAXE 200704
#define MAXE_H ((size_t)MAXE * H)
#define MAXE_I ((size_t)MAXE * INTC)

// fp32 scratch
__device__ float g_buf0[MAXE_H];     // x_ji
__device__ float g_buf1[MAXE_H];     // rbf_e
__device__ float g_down[MAXE_I];
__device__ float g_agg[MAXE_I];
__device__ float g_Wr[NRAD * H];
// fp16 split pairs (activations)
__device__ __half g_P0h[MAXE_H], g_P0l[MAXE_H];
__device__ __half g_P1h[MAXE_H], g_P1l[MAXE_H];
__device__ __half g_P2h[MAXE_H], g_P2l[MAXE_H];
__device__ __half g_aggh[MAXE_I], g_aggl[MAXE_I];
// fp16 split weights, fragment-permuted; slot = 65536 halves; 2w=hi, 2w+1=lo
__device__ __half g_Wsp[22 * 65536];

__device__ __forceinline__ float silu(float v) {
    return v / (1.0f + __expf(-v));
}
__device__ __forceinline__ void h_split(float v, __half& h, __half& l) {
    h = __float2half_rn(v);
    l = __float2half_rn(v - __half2float(h));
}

__device__ __forceinline__ void mma_f16(float* d, const uint32_t* a, const uint32_t* b) {
    asm volatile(
        "mma.sync.aligned.m16n8k16.row.col.f32.f16.f16.f32 "
        "{%0,%1,%2,%3},{%4,%5,%6,%7},{%8,%9},{%0,%1,%2,%3};\n"
        : "+f"(d[0]), "+f"(d[1]), "+f"(d[2]), "+f"(d[3])
        : "r"(a[0]), "r"(a[1]), "r"(a[2]), "r"(a[3]), "r"(b[0]), "r"(b[1]));
}

__device__ __forceinline__ uint32_t smem_u32(const void* p) {
    uint32_t a;
    asm("{ .reg .u64 t; cvta.to.shared.u64 t, %1; cvt.u32.u64 %0, t; }" : "=r"(a) : "l"(p));
    return a;
}
__device__ __forceinline__ void cp_async16(uint32_t dst, const void* src, int szr) {
    asm volatile("cp.async.cg.shared.global [%0], [%1], 16, %2;"
                 :: "r"(dst), "l"(src), "r"(szr) : "memory");
}
#define CP_COMMIT() asm volatile("cp.async.commit_group;" ::: "memory")
#define CP_WAIT(n)  asm volatile("cp.async.wait_group %0;" :: "n"(n) : "memory")

// ---------------------------------------------------------------------------
// GEMM config: BM=128, BN=128, BK=16 (one k16 mma step), 512 thr, 4 stages
// smem layout (bytes): Ahi s*6144 | Alo 24576+s*6144 | Bhi 49152+s*4096 |
//                      Blo 65536+s*4096 ; total 81920
// ---------------------------------------------------------------------------
#define BM 128
#define BN 128
#define BK 16
#define STAGES 4
#define A_STG 6144
#define B_STG 4096
#define ALO_OFF 24576
#define BHI_OFF 49152
#define BLO_OFF 65536
#define SMEM_BYTES 81920

__device__ __forceinline__ void issue_tile(
    uint32_t s0, const __half* __restrict__ Ah, const __half* __restrict__ Al,
    const __half* __restrict__ Bh, const __half* __restrict__ Bl,
    int rowBase, int cblk0, int ncblk, int M, int K, int kt, int s, int tid) {
    const int t2 = tid & 255;
    if (tid < 256) {
        // A hi chunk
        const int r = t2 >> 1, c = t2 & 1;
        const int gr = rowBase + r;
        const bool v = gr < M;
        const __half* src = Ah + (size_t)(v ? gr : 0) * K + kt * 16 + c * 8;
        cp_async16(s0 + (uint32_t)(s * A_STG + r * 48 + c * 16), src, v ? 16 : 0);
        // B hi chunk
        const int cblkL = t2 >> 6, rr = (t2 >> 5) & 1, lane = t2 & 31;
        const size_t goff = ((size_t)((kt * ncblk + cblk0 + cblkL) * 2 + rr) * 32 + lane) * 8;
        cp_async16(s0 + (uint32_t)(BHI_OFF + s * B_STG + t2 * 16), Bh + goff, 16);
    } else {
        const int r = t2 >> 1, c = t2 & 1;
        const int gr = rowBase + r;
        const bool v = gr < M;
        const __half* src = Al + (size_t)(v ? gr : 0) * K + kt * 16 + c * 8;
        cp_async16(s0 + (uint32_t)(ALO_OFF + s * A_STG + r * 48 + c * 16), src, v ? 16 : 0);
        const int cblkL = t2 >> 6, rr = (t2 >> 5) & 1, lane = t2 & 31;
        const size_t goff = ((size_t)((kt * ncblk + cblk0 + cblkL) * 2 + rr) * 32 + lane) * 8;
        cp_async16(s0 + (uint32_t)(BLO_OFF + s * B_STG + t2 * 16), Bl + goff, 16);
    }
}

__global__ void __launch_bounds__(512, 1) gemm_f16x2(
    const __half* __restrict__ Ah, const __half* __restrict__ Al,
    const __half* __restrict__ Bh, const __half* __restrict__ Bl,
    const float* __restrict__ bias, const float* __restrict__ mul,
    const float* __restrict__ addF,
    const __half* __restrict__ addH, const __half* __restrict__ addL,
    float* __restrict__ Cf, __half* __restrict__ Chi, __half* __restrict__ Clo,
    int M, int N, int K, int ncblk) {

    extern __shared__ char smem_raw[];
    char* bp = smem_raw;
    const uint32_t s0 = smem_u32(smem_raw);

    const int tid  = threadIdx.x;
    const int wid  = tid >> 5;
    const int lane = tid & 31;
    const int g    = lane >> 2;
    const int t    = lane & 3;
    const int wy   = wid >> 2;
    const int wx   = wid & 3;

    const int rowBase = blockIdx.x * BM;
    const int colBase = blockIdx.y * BN;
    const int cblk0   = colBase >> 5;

    float acc[2][4][4];
    #pragma unroll
    for (int i = 0; i < 2; i++)
        #pragma unroll
        for (int j = 0; j < 4; j++)
            #pragma unroll
            for (int r = 0; r < 4; r++) acc[i][j][r] = 0.f;

    const int nk = K / BK;
    #pragma unroll
    for (int s = 0; s < STAGES - 1; s++) {
        if (s < nk) {
            issue_tile(s0, Ah, Al, Bh, Bl, rowBase, cblk0, ncblk, M, K, s, s, tid);
            CP_COMMIT();
        }
    }

    for (int it = 0; it < nk; ++it) {
        const int pend = nk - 1 - it;
        if (pend >= 2)      CP_WAIT(2);
        else if (pend == 1) CP_WAIT(1);
        else                CP_WAIT(0);
        __syncthreads();

        const int nx = it + STAGES - 1;
        if (nx < nk) {
            issue_tile(s0, Ah, Al, Bh, Bl, rowBase, cblk0, ncblk, M, K, nx, nx % STAGES, tid);
            CP_COMMIT();
        }

        const int s = it % STAGES;

        // B fragments: 2 LDS.128 per hi/lo
        uint4 vh0 = *reinterpret_cast<uint4*>(bp + BHI_OFF + s * B_STG + ((wx * 2 + 0) * 32 + lane) * 16);
        uint4 vh1 = *reinterpret_cast<uint4*>(bp + BHI_OFF + s * B_STG + ((wx * 2 + 1) * 32 + lane) * 16);
        uint4 vl0 = *reinterpret_cast<uint4*>(bp + BLO_OFF + s * B_STG + ((wx * 2 + 0) * 32 + lane) * 16);
        uint4 vl1 = *reinterpret_cast<uint4*>(bp + BLO_OFF + s * B_STG + ((wx * 2 + 1) * 32 + lane) * 16);
        uint32_t bh[4][2], bl[4][2];
        bh[0][0] = vh0.x; bh[1][0] = vh0.y; bh[2][0] = vh0.z; bh[3][0] = vh0.w;
        bh[0][1] = vh1.x; bh[1][1] = vh1.y; bh[2][1] = vh1.z; bh[3][1] = vh1.w;
        bl[0][0] = vl0.x; bl[1][0] = vl0.y; bl[2][0] = vl0.z; bl[3][0] = vl0.w;
        bl[0][1] = vl1.x; bl[1][1] = vl1.y; bl[2][1] = vl1.z; bl[3][1] = vl1.w;

        #pragma unroll
        for (int mt = 0; mt < 2; mt++) {
            const int m0 = wy * 32 + mt * 16;
            char* arh = bp + s * A_STG + (m0 + g) * 48 + t * 4;
            char* arl = bp + ALO_OFF + s * A_STG + (m0 + g) * 48 + t * 4;
            uint32_t ah[4], al[4];
            ah[0] = *reinterpret_cast<uint32_t*>(arh);
            ah[1] = *reinterpret_cast<uint32_t*>(arh + 8 * 48);
            ah[2] = *reinterpret_cast<uint32_t*>(arh + 16);
            ah[3] = *reinterpret_cast<uint32_t*>(arh + 8 * 48 + 16);
            al[0] = *reinterpret_cast<uint32_t*>(arl);
            al[1] = *reinterpret_cast<uint32_t*>(arl + 8 * 48);
            al[2] = *reinterpret_cast<uint32_t*>(arl + 16);
            al[3] = *reinterpret_cast<uint32_t*>(arl + 8 * 48 + 16);
            #pragma unroll
            for (int nt = 0; nt < 4; nt++) {
                mma_f16(acc[mt][nt], al, bh[nt]);
                mma_f16(acc[mt][nt], ah, bl[nt]);
                mma_f16(acc[mt][nt], ah, bh[nt]);
            }
        }
    }

    // epilogue: (+bias) -> silu -> (*mul) -> (+add) -> {Cf, (Chi,Clo)}
    #pragma unroll
    for (int mt = 0; mt < 2; mt++) {
        #pragma unroll
        for (int nt = 0; nt < 4; nt++) {
            const int c0 = colBase + wx * 32 + nt * 8 + 2 * t;
            if (c0 >= N) continue;
            #pragma unroll
            for (int half = 0; half < 2; half++) {
                const int row = rowBase + wy * 32 + mt * 16 + g + 8 * half;
                if (row >= M) continue;
                const size_t idx = (size_t)row * N + c0;
                float v0 = acc[mt][nt][half * 2];
                float v1 = acc[mt][nt][half * 2 + 1];
                if (bias) { v0 += bias[c0]; v1 += bias[c0 + 1]; }
                v0 = silu(v0); v1 = silu(v1);
                if (mul)  { v0 *= mul[idx];  v1 *= mul[idx + 1]; }
                if (addF) { v0 += addF[idx]; v1 += addF[idx + 1]; }
                if (addH) {
                    v0 += __half2float(addH[idx]) + __half2float(addL[idx]);
                    v1 += __half2float(addH[idx + 1]) + __half2float(addL[idx + 1]);
                }
                if (Cf) { Cf[idx] = v0; Cf[idx + 1] = v1; }
                if (Chi) {
                    __half h0, l0, h1, l1;
                    h_split(v0, h0, l0); h_split(v1, h1, l1);
                    *reinterpret_cast<__half2*>(Chi + idx) = __halves2half2(h0, h1);
                    *reinterpret_cast<__half2*>(Clo + idx) = __halves2half2(l0, l1);
                }
            }
        }
    }
}

// ---------------------------------------------------------------------------
// Prep: split+permute ALL weights into fp16 hi/lo fragment layout (one launch)
// out b32 index: ((kb*ncblk + cblk)*2 + r)*128 + lane*4 + nt
//   k0 = kb*16 + r*8 + t*2 ; n = cblk*32 + nt*8 + g ; halves (k0, k0+1)
// ---------------------------------------------------------------------------
__global__ void split_w_kernel(
    const float* p0, const float* p1, const float* p2, const float* p3,
    const float* p4, const float* p5, const float* p6, const float* p7,
    const float* p8, const float* p9, const float* p10) {
    const float* srcs[11] = {p0, p1, p2, p3, p4, p5, p6, p7, p8, p9, p10};
    // {K, N(actual), ncblk(stored)}
    const int KK[11]  = {256, 256, 256, 64, 256, 256, 256, 256, 256, 256, 256};
    const int NN[11]  = {256, 256, 64, 256, 256, 256, 256, 256, 256, 256, 256};
    const int NC[11]  = {8, 8, 4, 8, 8, 8, 8, 8, 8, 8, 8};
    const int w = blockIdx.y;
    const int i = blockIdx.x * 256 + threadIdx.x;
    const int K = KK[w], N = NN[w], ncblk = NC[w];
    const int total = (K / 16) * ncblk * 256;
    if (i >= total) return;
    const int kb = i / (ncblk * 256);
    const int rem = i % (ncblk * 256);
    const int cblk = rem >> 8;
    const int j = rem & 255;
    const int r = j >> 7, lane = (j >> 2) & 31, nt = j & 3;
    const int gg = lane >> 2, tt = lane & 3;
    const int k0 = kb * 16 + r * 8 + tt * 2;
    const int n  = cblk * 32 + nt * 8 + gg;
    const float* W = srcs[w];
    float v0 = (n < N && k0 < K)     ? W[(size_t)k0 * N + n]       : 0.f;
    float v1 = (n < N && k0 + 1 < K) ? W[(size_t)(k0 + 1) * N + n] : 0.f;
    __half h0, l0, h1, l1;
    h_split(v0, h0, l0); h_split(v1, h1, l1);
    const size_t o = (size_t)i * 2;   // halves index within slot
    __half* hi = g_Wsp + (size_t)(2 * w) * 65536;
    __half* lo = g_Wsp + (size_t)(2 * w + 1) * 65536;
    *reinterpret_cast<__half2*>(hi + o) = __halves2half2(h0, h1);
    *reinterpret_cast<__half2*>(lo + o) = __halves2half2(l0, l1);
}

// element-wise fp32 -> (hi,lo) fp16 split
__global__ void split_pair_kernel(const float* __restrict__ src,
                                  __half* __restrict__ hi, __half* __restrict__ lo,
                                  int n4) {
    int i = blockIdx.x * 256 + threadIdx.x;
    if (i < n4) {
        float4 v = reinterpret_cast<const float4*>(src)[i];
        __half h0, l0, h1, l1, h2, l2, h3, l3;
        h_split(v.x, h0, l0); h_split(v.y, h1, l1);
        h_split(v.z, h2, l2); h_split(v.w, h3, l3);
        reinterpret_cast<__half2*>(hi)[i * 2]     = __halves2half2(h0, h1);
        reinterpret_cast<__half2*>(hi)[i * 2 + 1] = __halves2half2(h2, h3);
        reinterpret_cast<__half2*>(lo)[i * 2]     = __halves2half2(l0, l1);
        reinterpret_cast<__half2*>(lo)[i * 2 + 1] = __halves2half2(l2, l3);
    }
}

__global__ void zero_agg_kernel(int n4) {
    int i = blockIdx.x * 256 + threadIdx.x;
    if (i < n4) reinterpret_cast<float4*>(g_agg)[i] = make_float4(0.f, 0.f, 0.f, 0.f);
}

// ---------------------------------------------------------------------------
// Tiny basis kernels
// ---------------------------------------------------------------------------
__global__ void wr_kernel(const float* __restrict__ W1, const float* __restrict__ W2) {
    int c = threadIdx.x;
    #pragma unroll
    for (int k = 0; k < NRAD; k++) {
        float v = 0.f;
        #pragma unroll
        for (int j = 0; j < BAS; j++) v += W1[k * BAS + j] * W2[j * H + c];
        g_Wr[k * H + c] = v;
    }
}

__global__ void __launch_bounds__(256) rbfe_kernel(
    const float* __restrict__ rbf, float* __restrict__ out, int E) {
    __shared__ float srbf[64 * NRAD];
    const int tid = threadIdx.x;
    const int e0 = blockIdx.x * 64;
    float w[NRAD];
    #pragma unroll
    for (int k = 0; k < NRAD; k++) w[k] = g_Wr[k * H + tid];
    for (int i = tid; i < 64 * NRAD; i += 256) {
        int e = e0 + i / NRAD;
        srbf[i] = (e < E) ? rbf[(size_t)e * NRAD + (i % NRAD)] : 0.f;
    }
    __syncthreads();
    for (int r = 0; r < 64; r++) {
        int e = e0 + r;
        if (e >= E) break;
        float v = 0.f;
        #pragma unroll
        for (int k = 0; k < NRAD; k++) v += w[k] * srbf[r * NRAD + k];
        out[(size_t)e * H + tid] = v;
    }
}

// ---------------------------------------------------------------------------
// Triplet scatter (R5 version: red.global.add.v4)
// ---------------------------------------------------------------------------
#define SC_TRI 32
__global__ void __launch_bounds__(512) scatter_v4_kernel(
    const float* __restrict__ sbf, const int* __restrict__ idx_kj,
    const int* __restrict__ idx_ji, const float* __restrict__ W1,
    const float* __restrict__ W2, int T) {
    __shared__ float W1s[SBF_DIM * BAS];
    __shared__ float W2s[BAS * INTC];
    __shared__ float sbfs[SC_TRI][SBF_DIM + 2];
    __shared__ float bs[SC_TRI][BAS];

    const int tid = threadIdx.x;
    for (int i = tid; i < SBF_DIM * BAS; i += 512) W1s[i] = W1[i];
    for (int i = tid; i < BAS * INTC; i += 512) W2s[i] = W2[i];

    const int t = tid >> 4;
    const int l = tid & 15;
    const long tri = (long)blockIdx.x * SC_TRI + t;
    const bool valid = tri < (long)T;

    if (valid) {
        #pragma unroll
        for (int i = l; i < SBF_DIM; i += 16) sbfs[t][i] = sbf[tri * SBF_DIM + i];
    }
    __syncthreads();

    if (valid && l < BAS) {
        float b = 0.f;
        #pragma unroll
        for (int j = 0; j < SBF_DIM; j++) b += sbfs[t][j] * W1s[j * BAS + l];
        bs[t][l] = b;
    }
    __syncthreads();

    if (valid) {
        const int c0 = l * 4;
        float s0 = 0.f, s1 = 0.f, s2 = 0.f, s3 = 0.f;
        #pragma unroll
        for (int k = 0; k < BAS; k++) {
            const float bk = bs[t][k];
            const float* w = &W2s[k * INTC + c0];
            s0 += bk * w[0]; s1 += bk * w[1]; s2 += bk * w[2]; s3 += bk * w[3];
        }
        const int kj = idx_kj[tri];
        const int ji = idx_ji[tri];
        const float4 d = __ldg(reinterpret_cast<const float4*>(&g_down[(size_t)kj * INTC + c0]));
        s0 *= d.x; s1 *= d.y; s2 *= d.z; s3 *= d.w;
        float* dst = &g_agg[(size_t)ji * INTC + c0];
        asm volatile("red.global.add.v4.f32 [%0], {%1,%2,%3,%4};"
                     :: "l"(dst), "f"(s0), "f"(s1), "f"(s2), "f"(s3) : "memory");
    }
}

// ---------------------------------------------------------------------------
// Host orchestration
// ---------------------------------------------------------------------------
struct Pair { __half* h; __half* l; };

static inline void launch_gemm(Pair A, const __half* bh, const __half* bl,
                               const float* bias, const float* mul, const float* addF,
                               Pair addP, float* Cf, Pair Cp,
                               int M, int N, int K, int ncblk) {
    dim3 grid((M + BM - 1) / BM, (N + BN - 1) / BN);
    gemm_f16x2<<<grid, 512, SMEM_BYTES>>>(A.h, A.l, bh, bl, bias, mul, addF,
                                          addP.h, addP.l, Cf, Cp.h, Cp.l,
                                          M, N, K, ncblk);
}

extern "C" void kernel_launch(void* const* d_in, const int* in_sizes, int n_in,
                              void* d_out, int out_size) {
    const float* x      = (const float*)d_in[0];
    const float* rbf    = (const float*)d_in[1];
    const float* sbf    = (const float*)d_in[2];
    const int*   idx_kj = (const int*)d_in[3];
    const int*   idx_ji = (const int*)d_in[4];
    const float* W_rbf1 = (const float*)d_in[5];
    const float* W_rbf2 = (const float*)d_in[6];
    const float* W_sbf1 = (const float*)d_in[7];
    const float* W_sbf2 = (const float*)d_in[8];
    const float* W_kj   = (const float*)d_in[9];
    const float* b_kj   = (const float*)d_in[10];
    const float* W_ji   = (const float*)d_in[11];
    const float* b_ji   = (const float*)d_in[12];
    const float* W_down = (const float*)d_in[13];
    const float* W_up   = (const float*)d_in[14];
    const float* rb_W1  = (const float*)d_in[15];
    const float* rb_b1  = (const float*)d_in[16];
    const float* rb_W2  = (const float*)d_in[17];
    const float* rb_b2  = (const float*)d_in[18];
    const float* W_lin  = (const float*)d_in[19];
    const float* b_lin  = (const float*)d_in[20];
    const float* ra_W1  = (const float*)d_in[21];
    const float* ra_b1  = (const float*)d_in[22];
    const float* ra_W2  = (const float*)d_in[23];
    const float* ra_b2  = (const float*)d_in[24];

    const int E = in_sizes[0] / H;
    const int T = in_sizes[3];
    float* out = (float*)d_out;

    cudaFuncSetAttribute(gemm_f16x2, cudaFuncAttributeMaxDynamicSharedMemorySize, SMEM_BYTES);

    float *buf0, *buf1, *down, *agg;
    __half *P0h, *P0l, *P1h, *P1l, *P2h, *P2l, *aggh, *aggl, *wsp;
    cudaGetSymbolAddress((void**)&buf0, g_buf0);
    cudaGetSymbolAddress((void**)&buf1, g_buf1);
    cudaGetSymbolAddress((void**)&down, g_down);
    cudaGetSymbolAddress((void**)&agg,  g_agg);
    cudaGetSymbolAddress((void**)&P0h, g_P0h); cudaGetSymbolAddress((void**)&P0l, g_P0l);
    cudaGetSymbolAddress((void**)&P1h, g_P1h); cudaGetSymbolAddress((void**)&P1l, g_P1l);
    cudaGetSymbolAddress((void**)&P2h, g_P2h); cudaGetSymbolAddress((void**)&P2l, g_P2l);
    cudaGetSymbolAddress((void**)&aggh, g_aggh); cudaGetSymbolAddress((void**)&aggl, g_aggl);
    cudaGetSymbolAddress((void**)&wsp, g_Wsp);
    #define WHI(w) (wsp + (size_t)(2 * (w)) * 65536)
    #define WLO(w) (wsp + (size_t)(2 * (w) + 1) * 65536)

    const Pair P0{P0h, P0l}, P1{P1h, P1l}, P2{P2h, P2l}, Pagg{aggh, aggl};
    const Pair NOP{nullptr, nullptr};

    // L1: weights split+permute  L2: wr  L3: zero agg  L4: rbf_e  L5: split x
    split_w_kernel<<<dim3(128, 11), 256>>>(
        W_ji, W_kj, W_down, W_up, rb_W1, rb_W2, W_lin, ra_W1, ra_W2,
        ra_W1 + (size_t)H * H, ra_W2 + (size_t)H * H);
    wr_kernel<<<1, 256>>>(W_rbf1, W_rbf2);
    zero_agg_kernel<<<(E * INTC / 4 + 255) / 256, 256>>>(E * INTC / 4);
    rbfe_kernel<<<(E + 63) / 64, 256>>>(rbf, buf1, E);
    split_pair_kernel<<<((E * H / 4) + 255) / 256, 256>>>(x, P0h, P0l, E * H / 4);

    // L6: x_ji (profiled launch)
    launch_gemm(P0, WHI(0), WLO(0), b_ji, nullptr, nullptr, NOP, buf0, NOP, E, H, H, 8);
    // t = silu(x@W_kj+b)*rbf_e -> split P1
    launch_gemm(P0, WHI(1), WLO(1), b_kj, buf1, nullptr, NOP, nullptr, P1, E, H, H, 8);
    // down = silu(t@W_down) -> fp32 g_down  (N=64, stored ncblk=4)
    launch_gemm(P1, WHI(2), WLO(2), nullptr, nullptr, nullptr, NOP, down, NOP, E, INTC, H, 4);

    scatter_v4_kernel<<<(T + SC_TRI - 1) / SC_TRI, 512>>>(sbf, idx_kj, idx_ji,
                                                          W_sbf1, W_sbf2, T);
    split_pair_kernel<<<((E * INTC / 4) + 255) / 256, 256>>>(agg, aggh, aggl, E * INTC / 4);

    // h0 = silu(agg@W_up) + x_ji -> split P2
    launch_gemm(Pagg, WHI(3), WLO(3), nullptr, nullptr, buf0, NOP, nullptr, P2, E, H, INTC, 8);
    // u = silu(h0@rbW1+b1) -> P1
    launch_gemm(P2, WHI(4), WLO(4), rb_b1, nullptr, nullptr, NOP, nullptr, P1, E, H, H, 8);
    // h1 = h0 + silu(u@rbW2+b2) -> P0
    launch_gemm(P1, WHI(5), WLO(5), rb_b2, nullptr, nullptr, P2, nullptr, P0, E, H, H, 8);
    // h2 = silu(h1@W_lin+b_lin) + x -> P2
    launch_gemm(P0, WHI(6), WLO(6), b_lin, nullptr, x, NOP, nullptr, P2, E, H, H, 8);
    // u2 = silu(h2@raW1+b1) -> P1
    launch_gemm(P2, WHI(7), WLO(7), ra_b1, nullptr, nullptr, NOP, nullptr, P1, E, H, H, 8);
    // h3 = h2 + silu(u2@raW2+b2) -> P0
    launch_gemm(P1, WHI(8), WLO(8), ra_b2, nullptr, nullptr, P2, nullptr, P0, E, H, H, 8);
    // u3 = silu(h3@raW1b+b1b) -> P1
    launch_gemm(P0, WHI(9), WLO(9), ra_b1 + H, nullptr, nullptr, NOP, nullptr, P1, E, H, H, 8);
    // out = h3 + silu(u3@raW2b+b2b) -> fp32 d_out
    launch_gemm(P1, WHI(10), WLO(10), ra_b2 + H, nullptr, nullptr, P0, out, NOP, E, H, H, 8);
}

// round 7
// speedup vs baseline: 2.1554x; 1.0499x over previous
#include <cuda_runtime.h>
#include <cuda_fp16.h>
#include <cstdint>

// ---------------------------------------------------------------------------
// InteractionPPBlock (DimeNet++) — round 7: 2xFP16-split GEMMs + ldmatrix A
// fragments, reordered launches so ncu captures the big GEMM
// ---------------------------------------------------------------------------

#define H 256
#define INTC 64
#define SBF_DIM 42
#define NRAD 6
#define BAS 8

#define MAXE 200704
#define MAXE_H ((size_t)MAXE * H)
#define MAXE_I ((size_t)MAXE * INTC)

__device__ float g_buf0[MAXE_H];     // x_ji
__device__ float g_buf1[MAXE_H];     // rbf_e
__device__ float g_down[MAXE_I];
__device__ float g_agg[MAXE_I];
__device__ float g_Wr[NRAD * H];
__device__ __half g_P0h[MAXE_H], g_P0l[MAXE_H];
__device__ __half g_P1h[MAXE_H], g_P1l[MAXE_H];
__device__ __half g_P2h[MAXE_H], g_P2l[MAXE_H];
__device__ __half g_aggh[MAXE_I], g_aggl[MAXE_I];
__device__ __half g_Wsp[22 * 65536];

__device__ __forceinline__ float silu(float v) {
    return v / (1.0f + __expf(-v));
}
__device__ __forceinline__ void h_split(float v, __half& h, __half& l) {
    h = __float2half_rn(v);
    l = __float2half_rn(v - __half2float(h));
}

__device__ __forceinline__ void mma_f16(float* d, const uint32_t* a, const uint32_t* b) {
    asm volatile(
        "mma.sync.aligned.m16n8k16.row.col.f32.f16.f16.f32 "
        "{%0,%1,%2,%3},{%4,%5,%6,%7},{%8,%9},{%0,%1,%2,%3};\n"
        : "+f"(d[0]), "+f"(d[1]), "+f"(d[2]), "+f"(d[3])
        : "r"(a[0]), "r"(a[1]), "r"(a[2]), "r"(a[3]), "r"(b[0]), "r"(b[1]));
}
__device__ __forceinline__ void ldsm_x4(uint32_t* r, uint32_t addr) {
    asm volatile("ldmatrix.sync.aligned.m8n8.x4.shared.b16 {%0,%1,%2,%3}, [%4];"
                 : "=r"(r[0]), "=r"(r[1]), "=r"(r[2]), "=r"(r[3]) : "r"(addr));
}

__device__ __forceinline__ uint32_t smem_u32(const void* p) {
    uint32_t a;
    asm("{ .reg .u64 t; cvta.to.shared.u64 t, %1; cvt.u32.u64 %0, t; }" : "=r"(a) : "l"(p));
    return a;
}
__device__ __forceinline__ void cp_async16(uint32_t dst, const void* src, int szr) {
    asm volatile("cp.async.cg.shared.global [%0], [%1], 16, %2;"
                 :: "r"(dst), "l"(src), "r"(szr) : "memory");
}
#define CP_COMMIT() asm volatile("cp.async.commit_group;" ::: "memory")
#define CP_WAIT(n)  asm volatile("cp.async.wait_group %0;" :: "n"(n) : "memory")

// ---------------------------------------------------------------------------
// GEMM config: BM=128, BN=128, BK=16, 512 thr, 4 stages
// ---------------------------------------------------------------------------
#define BM 128
#define BN 128
#define BK 16
#define STAGES 4
#define A_STG 6144
#define B_STG 4096
#define ALO_OFF 24576
#define BHI_OFF 49152
#define BLO_OFF 65536
#define SMEM_BYTES 81920

__device__ __forceinline__ void issue_tile(
    uint32_t s0, const __half* __restrict__ Ah, const __half* __restrict__ Al,
    const __half* __restrict__ Bh, const __half* __restrict__ Bl,
    int rowBase, int cblk0, int ncblk, int M, int K, int kt, int s, int tid) {
    const int t2 = tid & 255;
    if (tid < 256) {
        const int r = t2 >> 1, c = t2 & 1;
        const int gr = rowBase + r;
        const bool v = gr < M;
        const __half* src = Ah + (size_t)(v ? gr : 0) * K + kt * 16 + c * 8;
        cp_async16(s0 + (uint32_t)(s * A_STG + r * 48 + c * 16), src, v ? 16 : 0);
        const int cblkL = t2 >> 6, rr = (t2 >> 5) & 1, lane = t2 & 31;
        const size_t goff = ((size_t)((kt * ncblk + cblk0 + cblkL) * 2 + rr) * 32 + lane) * 8;
        cp_async16(s0 + (uint32_t)(BHI_OFF + s * B_STG + t2 * 16), Bh + goff, 16);
    } else {
        const int r = t2 >> 1, c = t2 & 1;
        const int gr = rowBase + r;
        const bool v = gr < M;
        const __half* src = Al + (size_t)(v ? gr : 0) * K + kt * 16 + c * 8;
        cp_async16(s0 + (uint32_t)(ALO_OFF + s * A_STG + r * 48 + c * 16), src, v ? 16 : 0);
        const int cblkL = t2 >> 6, rr = (t2 >> 5) & 1, lane = t2 & 31;
        const size_t goff = ((size_t)((kt * ncblk + cblk0 + cblkL) * 2 + rr) * 32 + lane) * 8;
        cp_async16(s0 + (uint32_t)(BLO_OFF + s * B_STG + t2 * 16), Bl + goff, 16);
    }
}

__global__ void __launch_bounds__(512, 1) gemm_f16x2(
    const __half* __restrict__ Ah, const __half* __restrict__ Al,
    const __half* __restrict__ Bh, const __half* __restrict__ Bl,
    const float* __restrict__ bias, const float* __restrict__ mul,
    const float* __restrict__ addF,
    const __half* __restrict__ addH, const __half* __restrict__ addL,
    float* __restrict__ Cf, __half* __restrict__ Chi, __half* __restrict__ Clo,
    int M, int N, int K, int ncblk) {

    extern __shared__ char smem_raw[];
    char* bp = smem_raw;
    const uint32_t s0 = smem_u32(smem_raw);

    const int tid  = threadIdx.x;
    const int wid  = tid >> 5;
    const int lane = tid & 31;
    const int g    = lane >> 2;
    const int t    = lane & 3;
    const int wy   = wid >> 2;
    const int wx   = wid & 3;

    const int rowBase = blockIdx.x * BM;
    const int colBase = blockIdx.y * BN;
    const int cblk0   = colBase >> 5;

    // ldmatrix source address (per lane), relative to A stage base:
    //   row = (lane&7) + ((lane&8)?8:0), col-halfstep = (lane&16)?16B:0
    const uint32_t lds_a_off =
        (uint32_t)(((lane & 7) + ((lane >> 3) & 1) * 8) * 48 + ((lane >> 4) & 1) * 16);

    float acc[2][4][4];
    #pragma unroll
    for (int i = 0; i < 2; i++)
        #pragma unroll
        for (int j = 0; j < 4; j++)
            #pragma unroll
            for (int r = 0; r < 4; r++) acc[i][j][r] = 0.f;

    const int nk = K / BK;
    #pragma unroll
    for (int s = 0; s < STAGES - 1; s++) {
        if (s < nk) {
            issue_tile(s0, Ah, Al, Bh, Bl, rowBase, cblk0, ncblk, M, K, s, s, tid);
            CP_COMMIT();
        }
    }

    for (int it = 0; it < nk; ++it) {
        const int pend = nk - 1 - it;
        if (pend >= 2)      CP_WAIT(2);
        else if (pend == 1) CP_WAIT(1);
        else                CP_WAIT(0);
        __syncthreads();

        const int nx = it + STAGES - 1;
        if (nx < nk) {
            issue_tile(s0, Ah, Al, Bh, Bl, rowBase, cblk0, ncblk, M, K, nx, nx % STAGES, tid);
            CP_COMMIT();
        }

        const int s = it % STAGES;

        // B fragments: 2 LDS.128 per hi/lo
        uint4 vh0 = *reinterpret_cast<uint4*>(bp + BHI_OFF + s * B_STG + ((wx * 2 + 0) * 32 + lane) * 16);
        uint4 vh1 = *reinterpret_cast<uint4*>(bp + BHI_OFF + s * B_STG + ((wx * 2 + 1) * 32 + lane) * 16);
        uint4 vl0 = *reinterpret_cast<uint4*>(bp + BLO_OFF + s * B_STG + ((wx * 2 + 0) * 32 + lane) * 16);
        uint4 vl1 = *reinterpret_cast<uint4*>(bp + BLO_OFF + s * B_STG + ((wx * 2 + 1) * 32 + lane) * 16);
        uint32_t bh[4][2], bl[4][2];
        bh[0][0] = vh0.x; bh[1][0] = vh0.y; bh[2][0] = vh0.z; bh[3][0] = vh0.w;
        bh[0][1] = vh1.x; bh[1][1] = vh1.y; bh[2][1] = vh1.z; bh[3][1] = vh1.w;
        bl[0][0] = vl0.x; bl[1][0] = vl0.y; bl[2][0] = vl0.z; bl[3][0] = vl0.w;
        bl[0][1] = vl1.x; bl[1][1] = vl1.y; bl[2][1] = vl1.z; bl[3][1] = vl1.w;

        #pragma unroll
        for (int mt = 0; mt < 2; mt++) {
            const int m0 = wy * 32 + mt * 16;
            uint32_t ah[4], al[4];
            ldsm_x4(ah, s0 + (uint32_t)(s * A_STG + m0 * 48) + lds_a_off);
            ldsm_x4(al, s0 + (uint32_t)(ALO_OFF + s * A_STG + m0 * 48) + lds_a_off);
            #pragma unroll
            for (int nt = 0; nt < 4; nt++) {
                mma_f16(acc[mt][nt], al, bh[nt]);
                mma_f16(acc[mt][nt], ah, bl[nt]);
                mma_f16(acc[mt][nt], ah, bh[nt]);
            }
        }
    }

    // epilogue
    #pragma unroll
    for (int mt = 0; mt < 2; mt++) {
        #pragma unroll
        for (int nt = 0; nt < 4; nt++) {
            const int c0 = colBase + wx * 32 + nt * 8 + 2 * t;
            if (c0 >= N) continue;
            #pragma unroll
            for (int half = 0; half < 2; half++) {
                const int row = rowBase + wy * 32 + mt * 16 + g + 8 * half;
                if (row >= M) continue;
                const size_t idx = (size_t)row * N + c0;
                float v0 = acc[mt][nt][half * 2];
                float v1 = acc[mt][nt][half * 2 + 1];
                if (bias) { v0 += bias[c0]; v1 += bias[c0 + 1]; }
                v0 = silu(v0); v1 = silu(v1);
                if (mul)  { v0 *= mul[idx];  v1 *= mul[idx + 1]; }
                if (addF) { v0 += addF[idx]; v1 += addF[idx + 1]; }
                if (addH) {
                    v0 += __half2float(addH[idx]) + __half2float(addL[idx]);
                    v1 += __half2float(addH[idx + 1]) + __half2float(addL[idx + 1]);
                }
                if (Cf) { Cf[idx] = v0; Cf[idx + 1] = v1; }
                if (Chi) {
                    __half h0, l0, h1, l1;
                    h_split(v0, h0, l0); h_split(v1, h1, l1);
                    *reinterpret_cast<__half2*>(Chi + idx) = __halves2half2(h0, h1);
                    *reinterpret_cast<__half2*>(Clo + idx) = __halves2half2(l0, l1);
                }
            }
        }
    }
}

// ---------------------------------------------------------------------------
// Prep kernels
// ---------------------------------------------------------------------------
__global__ void split_w_kernel(
    const float* p0, const float* p1, const float* p2, const float* p3,
    const float* p4, const float* p5, const float* p6, const float* p7,
    const float* p8, const float* p9, const float* p10) {
    const float* srcs[11] = {p0, p1, p2, p3, p4, p5, p6, p7, p8, p9, p10};
    const int KK[11]  = {256, 256, 256, 64, 256, 256, 256, 256, 256, 256, 256};
    const int NN[11]  = {256, 256, 64, 256, 256, 256, 256, 256, 256, 256, 256};
    const int NC[11]  = {8, 8, 4, 8, 8, 8, 8, 8, 8, 8, 8};
    const int w = blockIdx.y;
    const int i = blockIdx.x * 256 + threadIdx.x;
    const int K = KK[w], N = NN[w], ncblk = NC[w];
    const int total = (K / 16) * ncblk * 256;
    if (i >= total) return;
    const int kb = i / (ncblk * 256);
    const int rem = i % (ncblk * 256);
    const int cblk = rem >> 8;
    const int j = rem & 255;
    const int r = j >> 7, lane = (j >> 2) & 31, nt = j & 3;
    const int gg = lane >> 2, tt = lane & 3;
    const int k0 = kb * 16 + r * 8 + tt * 2;
    const int n  = cblk * 32 + nt * 8 + gg;
    const float* W = srcs[w];
    float v0 = (n < N && k0 < K)     ? W[(size_t)k0 * N + n]       : 0.f;
    float v1 = (n < N && k0 + 1 < K) ? W[(size_t)(k0 + 1) * N + n] : 0.f;
    __half h0, l0, h1, l1;
    h_split(v0, h0, l0); h_split(v1, h1, l1);
    const size_t o = (size_t)i * 2;
    __half* hi = g_Wsp + (size_t)(2 * w) * 65536;
    __half* lo = g_Wsp + (size_t)(2 * w + 1) * 65536;
    *reinterpret_cast<__half2*>(hi + o) = __halves2half2(h0, h1);
    *reinterpret_cast<__half2*>(lo + o) = __halves2half2(l0, l1);
}

__global__ void split_pair_kernel(const float* __restrict__ src,
                                  __half* __restrict__ hi, __half* __restrict__ lo,
                                  int n4) {
    int i = blockIdx.x * 256 + threadIdx.x;
    if (i < n4) {
        float4 v = reinterpret_cast<const float4*>(src)[i];
        __half h0, l0, h1, l1, h2, l2, h3, l3;
        h_split(v.x, h0, l0); h_split(v.y, h1, l1);
        h_split(v.z, h2, l2); h_split(v.w, h3, l3);
        reinterpret_cast<__half2*>(hi)[i * 2]     = __halves2half2(h0, h1);
        reinterpret_cast<__half2*>(hi)[i * 2 + 1] = __halves2half2(h2, h3);
        reinterpret_cast<__half2*>(lo)[i * 2]     = __halves2half2(l0, l1);
        reinterpret_cast<__half2*>(lo)[i * 2 + 1] = __halves2half2(l2, l3);
    }
}

__global__ void zero_agg_kernel(int n4) {
    int i = blockIdx.x * 256 + threadIdx.x;
    if (i < n4) reinterpret_cast<float4*>(g_agg)[i] = make_float4(0.f, 0.f, 0.f, 0.f);
}

__global__ void wr_kernel(const float* __restrict__ W1, const float* __restrict__ W2) {
    int c = threadIdx.x;
    #pragma unroll
    for (int k = 0; k < NRAD; k++) {
        float v = 0.f;
        #pragma unroll
        for (int j = 0; j < BAS; j++) v += W1[k * BAS + j] * W2[j * H + c];
        g_Wr[k * H + c] = v;
    }
}

__global__ void __launch_bounds__(256) rbfe_kernel(
    const float* __restrict__ rbf, float* __restrict__ out, int E) {
    __shared__ float srbf[64 * NRAD];
    const int tid = threadIdx.x;
    const int e0 = blockIdx.x * 64;
    float w[NRAD];
    #pragma unroll
    for (int k = 0; k < NRAD; k++) w[k] = g_Wr[k * H + tid];
    for (int i = tid; i < 64 * NRAD; i += 256) {
        int e = e0 + i / NRAD;
        srbf[i] = (e < E) ? rbf[(size_t)e * NRAD + (i % NRAD)] : 0.f;
    }
    __syncthreads();
    for (int r = 0; r < 64; r++) {
        int e = e0 + r;
        if (e >= E) break;
        float v = 0.f;
        #pragma unroll
        for (int k = 0; k < NRAD; k++) v += w[k] * srbf[r * NRAD + k];
        out[(size_t)e * H + tid] = v;
    }
}

// ---------------------------------------------------------------------------
// Triplet scatter (red.global.add.v4)
// ---------------------------------------------------------------------------
#define SC_TRI 32
__global__ void __launch_bounds__(512) scatter_v4_kernel(
    const float* __restrict__ sbf, const int* __restrict__ idx_kj,
    const int* __restrict__ idx_ji, const float* __restrict__ W1,
    const float* __restrict__ W2, int T) {
    __shared__ float W1s[SBF_DIM * BAS];
    __shared__ float W2s[BAS * INTC];
    __shared__ float sbfs[SC_TRI][SBF_DIM + 2];
    __shared__ float bs[SC_TRI][BAS];

    const int tid = threadIdx.x;
    for (int i = tid; i < SBF_DIM * BAS; i += 512) W1s[i] = W1[i];
    for (int i = tid; i < BAS * INTC; i += 512) W2s[i] = W2[i];

    const int t = tid >> 4;
    const int l = tid & 15;
    const long tri = (long)blockIdx.x * SC_TRI + t;
    const bool valid = tri < (long)T;

    if (valid) {
        #pragma unroll
        for (int i = l; i < SBF_DIM; i += 16) sbfs[t][i] = sbf[tri * SBF_DIM + i];
    }
    __syncthreads();

    if (valid && l < BAS) {
        float b = 0.f;
        #pragma unroll
        for (int j = 0; j < SBF_DIM; j++) b += sbfs[t][j] * W1s[j * BAS + l];
        bs[t][l] = b;
    }
    __syncthreads();

    if (valid) {
        const int c0 = l * 4;
        float s0 = 0.f, s1 = 0.f, s2 = 0.f, s3 = 0.f;
        #pragma unroll
        for (int k = 0; k < BAS; k++) {
            const float bk = bs[t][k];
            const float* w = &W2s[k * INTC + c0];
            s0 += bk * w[0]; s1 += bk * w[1]; s2 += bk * w[2]; s3 += bk * w[3];
        }
        const int kj = idx_kj[tri];
        const int ji = idx_ji[tri];
        const float4 d = __ldg(reinterpret_cast<const float4*>(&g_down[(size_t)kj * INTC + c0]));
        s0 *= d.x; s1 *= d.y; s2 *= d.z; s3 *= d.w;
        float* dst = &g_agg[(size_t)ji * INTC + c0];
        asm volatile("red.global.add.v4.f32 [%0], {%1,%2,%3,%4};"
                     :: "l"(dst), "f"(s0), "f"(s1), "f"(s2), "f"(s3) : "memory");
    }
}

// ---------------------------------------------------------------------------
// Host orchestration
// ---------------------------------------------------------------------------
struct Pair { __half* h; __half* l; };

static inline void launch_gemm(Pair A, const __half* bh, const __half* bl,
                               const float* bias, const float* mul, const float* addF,
                               Pair addP, float* Cf, Pair Cp,
                               int M, int N, int K, int ncblk) {
    dim3 grid((M + BM - 1) / BM, (N + BN - 1) / BN);
    gemm_f16x2<<<grid, 512, SMEM_BYTES>>>(A.h, A.l, bh, bl, bias, mul, addF,
                                          addP.h, addP.l, Cf, Cp.h, Cp.l,
                                          M, N, K, ncblk);
}

extern "C" void kernel_launch(void* const* d_in, const int* in_sizes, int n_in,
                              void* d_out, int out_size) {
    const float* x      = (const float*)d_in[0];
    const float* rbf    = (const float*)d_in[1];
    const float* sbf    = (const float*)d_in[2];
    const int*   idx_kj = (const int*)d_in[3];
    const int*   idx_ji = (const int*)d_in[4];
    const float* W_rbf1 = (const float*)d_in[5];
    const float* W_rbf2 = (const float*)d_in[6];
    const float* W_sbf1 = (const float*)d_in[7];
    const float* W_sbf2 = (const float*)d_in[8];
    const float* W_kj   = (const float*)d_in[9];
    const float* b_kj   = (const float*)d_in[10];
    const float* W_ji   = (const float*)d_in[11];
    const float* b_ji   = (const float*)d_in[12];
    const float* W_down = (const float*)d_in[13];
    const float* W_up   = (const float*)d_in[14];
    const float* rb_W1  = (const float*)d_in[15];
    const float* rb_b1  = (const float*)d_in[16];
    const float* rb_W2  = (const float*)d_in[17];
    const float* rb_b2  = (const float*)d_in[18];
    const float* W_lin  = (const float*)d_in[19];
    const float* b_lin  = (const float*)d_in[20];
    const float* ra_W1  = (const float*)d_in[21];
    const float* ra_b1  = (const float*)d_in[22];
    const float* ra_W2  = (const float*)d_in[23];
    const float* ra_b2  = (const float*)d_in[24];

    const int E = in_sizes[0] / H;
    const int T = in_sizes[3];
    float* out = (float*)d_out;

    cudaFuncSetAttribute(gemm_f16x2, cudaFuncAttributeMaxDynamicSharedMemorySize, SMEM_BYTES);

    float *buf0, *buf1, *down, *agg;
    __half *P0h, *P0l, *P1h, *P1l, *P2h, *P2l, *aggh, *aggl, *wsp;
    cudaGetSymbolAddress((void**)&buf0, g_buf0);
    cudaGetSymbolAddress((void**)&buf1, g_buf1);
    cudaGetSymbolAddress((void**)&down, g_down);
    cudaGetSymbolAddress((void**)&agg,  g_agg);
    cudaGetSymbolAddress((void**)&P0h, g_P0h); cudaGetSymbolAddress((void**)&P0l, g_P0l);
    cudaGetSymbolAddress((void**)&P1h, g_P1h); cudaGetSymbolAddress((void**)&P1l, g_P1l);
    cudaGetSymbolAddress((void**)&P2h, g_P2h); cudaGetSymbolAddress((void**)&P2l, g_P2l);
    cudaGetSymbolAddress((void**)&aggh, g_aggh); cudaGetSymbolAddress((void**)&aggl, g_aggl);
    cudaGetSymbolAddress((void**)&wsp, g_Wsp);
    #define WHI(w) (wsp + (size_t)(2 * (w)) * 65536)
    #define WLO(w) (wsp + (size_t)(2 * (w) + 1) * 65536)

    const Pair P0{P0h, P0l}, P1{P1h, P1l}, P2{P2h, P2l}, Pagg{aggh, aggl};
    const Pair NOP{nullptr, nullptr};

    // L1 split_w  L2 wr  L3 split x  L4 = BIG GEMM (ncu capture slot)
    split_w_kernel<<<dim3(128, 11), 256>>>(
        W_ji, W_kj, W_down, W_up, rb_W1, rb_W2, W_lin, ra_W1, ra_W2,
        ra_W1 + (size_t)H * H, ra_W2 + (size_t)H * H);
    wr_kernel<<<1, 256>>>(W_rbf1, W_rbf2);
    split_pair_kernel<<<((E * H / 4) + 255) / 256, 256>>>(x, P0h, P0l, E * H / 4);

    // L4: x_ji
    launch_gemm(P0, WHI(0), WLO(0), b_ji, nullptr, nullptr, NOP, buf0, NOP, E, H, H, 8);
    // L5: rbf_e   L6: zero agg
    rbfe_kernel<<<(E + 63) / 64, 256>>>(rbf, buf1, E);
    zero_agg_kernel<<<(E * INTC / 4 + 255) / 256, 256>>>(E * INTC / 4);
    // t = silu(x@W_kj+b)*rbf_e -> P1
    launch_gemm(P0, WHI(1), WLO(1), b_kj, buf1, nullptr, NOP, nullptr, P1, E, H, H, 8);
    // down = silu(t@W_down) -> fp32
    launch_gemm(P1, WHI(2), WLO(2), nullptr, nullptr, nullptr, NOP, down, NOP, E, INTC, H, 4);

    scatter_v4_kernel<<<(T + SC_TRI - 1) / SC_TRI, 512>>>(sbf, idx_kj, idx_ji,
                                                          W_sbf1, W_sbf2, T);
    split_pair_kernel<<<((E * INTC / 4) + 255) / 256, 256>>>(agg, aggh, aggl, E * INTC / 4);

    // h0 = silu(agg@W_up) + x_ji -> P2
    launch_gemm(Pagg, WHI(3), WLO(3), nullptr, nullptr, buf0, NOP, nullptr, P2, E, H, INTC, 8);
    // u = silu(h0@rbW1+b1) -> P1
    launch_gemm(P2, WHI(4), WLO(4), rb_b1, nullptr, nullptr, NOP, nullptr, P1, E, H, H, 8);
    // h1 = h0 + silu(u@rbW2+b2) -> P0
    launch_gemm(P1, WHI(5), WLO(5), rb_b2, nullptr, nullptr, P2, nullptr, P0, E, H, H, 8);
    // h2 = silu(h1@W_lin+b_lin) + x -> P2
    launch_gemm(P0, WHI(6), WLO(6), b_lin, nullptr, x, NOP, nullptr, P2, E, H, H, 8);
    // u2 = silu(h2@raW1+b1) -> P1
    launch_gemm(P2, WHI(7), WLO(7), ra_b1, nullptr, nullptr, NOP, nullptr, P1, E, H, H, 8);
    // h3 = h2 + silu(u2@raW2+b2) -> P0
    launch_gemm(P1, WHI(8), WLO(8), ra_b2, nullptr, nullptr, P2, nullptr, P0, E, H, H, 8);
    // u3 = silu(h3@raW1b+b1b) -> P1
    launch_gemm(P0, WHI(9), WLO(9), ra_b1 + H, nullptr, nullptr, NOP, nullptr, P1, E, H, H, 8);
    // out = h3 + silu(u3@raW2b+b2b) -> fp32 d_out
    launch_gemm(P1, WHI(10), WLO(10), ra_b2 + H, nullptr, nullptr, P0, out, NOP, E, H, H, 8);
}

// round 8
// speedup vs baseline: 2.3222x; 1.0774x over previous
#include <cuda_runtime.h>
#include <cuda_fp16.h>
#include <cstdint>

// ---------------------------------------------------------------------------
// InteractionPPBlock (DimeNet++) — round 8: 2xFP16-split GEMMs, 256-thr CTAs
// (2 CTAs/SM for cross-CTA latency hiding), hoisted cp.async addressing
// ---------------------------------------------------------------------------

#define H 256
#define INTC 64
#define SBF_DIM 42
#define NRAD 6
#define BAS 8

#define MAXE 200704
#define MAXE_H ((size_t)MAXE * H)
#define MAXE_I ((size_t)MAXE * INTC)

__device__ float g_buf0[MAXE_H];     // x_ji
__device__ float g_buf1[MAXE_H];     // rbf_e
__device__ float g_down[MAXE_I];
__device__ float g_agg[MAXE_I];
__device__ float g_Wr[NRAD * H];
__device__ __half g_P0h[MAXE_H], g_P0l[MAXE_H];
__device__ __half g_P1h[MAXE_H], g_P1l[MAXE_H];
__device__ __half g_P2h[MAXE_H], g_P2l[MAXE_H];
__device__ __half g_aggh[MAXE_I], g_aggl[MAXE_I];
__device__ __half g_Wsp[22 * 65536];

__device__ __forceinline__ float silu(float v) {
    return v / (1.0f + __expf(-v));
}
__device__ __forceinline__ void h_split(float v, __half& h, __half& l) {
    h = __float2half_rn(v);
    l = __float2half_rn(v - __half2float(h));
}

__device__ __forceinline__ void mma_f16(float* d, const uint32_t* a, const uint32_t* b) {
    asm volatile(
        "mma.sync.aligned.m16n8k16.row.col.f32.f16.f16.f32 "
        "{%0,%1,%2,%3},{%4,%5,%6,%7},{%8,%9},{%0,%1,%2,%3};\n"
        : "+f"(d[0]), "+f"(d[1]), "+f"(d[2]), "+f"(d[3])
        : "r"(a[0]), "r"(a[1]), "r"(a[2]), "r"(a[3]), "r"(b[0]), "r"(b[1]));
}
__device__ __forceinline__ void ldsm_x4(uint32_t* r, uint32_t addr) {
    asm volatile("ldmatrix.sync.aligned.m8n8.x4.shared.b16 {%0,%1,%2,%3}, [%4];"
                 : "=r"(r[0]), "=r"(r[1]), "=r"(r[2]), "=r"(r[3]) : "r"(addr));
}

__device__ __forceinline__ uint32_t smem_u32(const void* p) {
    uint32_t a;
    asm("{ .reg .u64 t; cvta.to.shared.u64 t, %1; cvt.u32.u64 %0, t; }" : "=r"(a) : "l"(p));
    return a;
}
__device__ __forceinline__ void cp_async16(uint32_t dst, const void* src, int szr) {
    asm volatile("cp.async.cg.shared.global [%0], [%1], 16, %2;"
                 :: "r"(dst), "l"(src), "r"(szr) : "memory");
}
#define CP_COMMIT() asm volatile("cp.async.commit_group;" ::: "memory")
#define CP_WAIT(n)  asm volatile("cp.async.wait_group %0;" :: "n"(n) : "memory")

// ---------------------------------------------------------------------------
// GEMM config: BM=128, BN=64, BK=16, 256 threads (8 warps 4x2), 4 stages
// stage block (16384 B): Ahi [0,6144) Alo [6144,12288) Bhi [12288,14336)
//                        Blo [14336,16384)
// ---------------------------------------------------------------------------
#define BM 128
#define BN 64
#define BK 16
#define STAGES 4
#define STG 16384
#define SMEM_BYTES (STAGES * STG)    // 65536

__global__ void __launch_bounds__(256, 2) gemm_f16x2(
    const __half* __restrict__ Ah, const __half* __restrict__ Al,
    const __half* __restrict__ Bh, const __half* __restrict__ Bl,
    const float* __restrict__ bias, const float* __restrict__ mul,
    const float* __restrict__ addF,
    const __half* __restrict__ addH, const __half* __restrict__ addL,
    float* __restrict__ Cf, __half* __restrict__ Chi, __half* __restrict__ Clo,
    int M, int N, int K, int ncblk) {

    extern __shared__ char smem_raw[];
    char* bp = smem_raw;
    const uint32_t s0 = smem_u32(smem_raw);

    const int tid  = threadIdx.x;
    const int wid  = tid >> 5;
    const int lane = tid & 31;
    const int g    = lane >> 2;
    const int t    = lane & 3;
    const int wy   = wid >> 1;    // 0..3
    const int wx   = wid & 1;     // 0..1

    const int rowBase = blockIdx.x * BM;
    const int colBase = blockIdx.y * BN;
    const int cblk0   = colBase >> 5;

    // ---- hoisted cp.async addressing ----
    const int ar = tid >> 1, ac = tid & 1;
    const int gr = rowBase + ar;
    const bool aV = gr < M;
    const __half* aSrcH = Ah + (size_t)(aV ? gr : 0) * K + ac * 8;
    const __half* aSrcL = Al + (size_t)(aV ? gr : 0) * K + ac * 8;
    const uint32_t aDstH = s0 + (uint32_t)(ar * 48 + ac * 16);
    const uint32_t aDstL = aDstH + 6144u;

    const int bj = tid & 127;
    const int cblkL = bj >> 6, brr = (bj >> 5) & 1, bln = bj & 31;
    const __half* bSrc = ((tid < 128) ? Bh : Bl)
        + ((size_t)((cblk0 + cblkL) * 2 + brr) * 32 + bln) * 8;
    const uint32_t bDst = s0 + 12288u + (tid < 128 ? 0u : 2048u) + (uint32_t)bj * 16;
    const size_t bStep = (size_t)ncblk * 512;    // halves per k-tile

    const uint32_t lds_a_off =
        (uint32_t)(((lane & 7) + ((lane >> 3) & 1) * 8) * 48 + ((lane >> 4) & 1) * 16);

    float acc[2][4][4];
    #pragma unroll
    for (int i = 0; i < 2; i++)
        #pragma unroll
        for (int j = 0; j < 4; j++)
            #pragma unroll
            for (int r = 0; r < 4; r++) acc[i][j][r] = 0.f;

    const int nk = K / BK;
    #pragma unroll
    for (int s = 0; s < STAGES - 1; s++) {
        if (s < nk) {
            cp_async16(aDstH + s * STG, aSrcH + s * 16, aV ? 16 : 0);
            cp_async16(aDstL + s * STG, aSrcL + s * 16, aV ? 16 : 0);
            cp_async16(bDst + s * STG, bSrc + (size_t)s * bStep, 16);
        }
        CP_COMMIT();
    }

    for (int it = 0; it < nk; ++it) {
        const int pend = nk - 1 - it;
        if (pend >= 2)      CP_WAIT(2);
        else if (pend == 1) CP_WAIT(1);
        else                CP_WAIT(0);
        __syncthreads();

        const int nx = it + STAGES - 1;
        if (nx < nk) {
            const uint32_t so = (uint32_t)(nx % STAGES) * STG;
            cp_async16(aDstH + so, aSrcH + nx * 16, aV ? 16 : 0);
            cp_async16(aDstL + so, aSrcL + nx * 16, aV ? 16 : 0);
            cp_async16(bDst + so, bSrc + (size_t)nx * bStep, 16);
            CP_COMMIT();
        }

        const uint32_t sb = (uint32_t)(it % STAGES) * STG;

        // B fragments: 2 LDS.128 per hi/lo (wx selects which cblk)
        uint4 vh0 = *reinterpret_cast<uint4*>(bp + sb + 12288 + ((wx * 2 + 0) * 32 + lane) * 16);
        uint4 vh1 = *reinterpret_cast<uint4*>(bp + sb + 12288 + ((wx * 2 + 1) * 32 + lane) * 16);
        uint4 vl0 = *reinterpret_cast<uint4*>(bp + sb + 14336 + ((wx * 2 + 0) * 32 + lane) * 16);
        uint4 vl1 = *reinterpret_cast<uint4*>(bp + sb + 14336 + ((wx * 2 + 1) * 32 + lane) * 16);
        uint32_t bh[4][2], bl[4][2];
        bh[0][0] = vh0.x; bh[1][0] = vh0.y; bh[2][0] = vh0.z; bh[3][0] = vh0.w;
        bh[0][1] = vh1.x; bh[1][1] = vh1.y; bh[2][1] = vh1.z; bh[3][1] = vh1.w;
        bl[0][0] = vl0.x; bl[1][0] = vl0.y; bl[2][0] = vl0.z; bl[3][0] = vl0.w;
        bl[0][1] = vl1.x; bl[1][1] = vl1.y; bl[2][1] = vl1.z; bl[3][1] = vl1.w;

        #pragma unroll
        for (int mt = 0; mt < 2; mt++) {
            const int m0 = wy * 32 + mt * 16;
            uint32_t ah[4], al[4];
            ldsm_x4(ah, s0 + sb + (uint32_t)(m0 * 48) + lds_a_off);
            ldsm_x4(al, s0 + sb + 6144u + (uint32_t)(m0 * 48) + lds_a_off);
            #pragma unroll
            for (int nt = 0; nt < 4; nt++) {
                mma_f16(acc[mt][nt], al, bh[nt]);
                mma_f16(acc[mt][nt], ah, bl[nt]);
                mma_f16(acc[mt][nt], ah, bh[nt]);
            }
        }
    }

    // epilogue
    #pragma unroll
    for (int mt = 0; mt < 2; mt++) {
        #pragma unroll
        for (int nt = 0; nt < 4; nt++) {
            const int c0 = colBase + wx * 32 + nt * 8 + 2 * t;
            if (c0 >= N) continue;
            #pragma unroll
            for (int half = 0; half < 2; half++) {
                const int row = rowBase + wy * 32 + mt * 16 + g + 8 * half;
                if (row >= M) continue;
                const size_t idx = (size_t)row * N + c0;
                float v0 = acc[mt][nt][half * 2];
                float v1 = acc[mt][nt][half * 2 + 1];
                if (bias) { v0 += bias[c0]; v1 += bias[c0 + 1]; }
                v0 = silu(v0); v1 = silu(v1);
                if (mul)  { v0 *= mul[idx];  v1 *= mul[idx + 1]; }
                if (addF) { v0 += addF[idx]; v1 += addF[idx + 1]; }
                if (addH) {
                    v0 += __half2float(addH[idx]) + __half2float(addL[idx]);
                    v1 += __half2float(addH[idx + 1]) + __half2float(addL[idx + 1]);
                }
                if (Cf) { Cf[idx] = v0; Cf[idx + 1] = v1; }
                if (Chi) {
                    __half h0, l0, h1, l1;
                    h_split(v0, h0, l0); h_split(v1, h1, l1);
                    *reinterpret_cast<__half2*>(Chi + idx) = __halves2half2(h0, h1);
                    *reinterpret_cast<__half2*>(Clo + idx) = __halves2half2(l0, l1);
                }
            }
        }
    }
}

// ---------------------------------------------------------------------------
// Prep kernels
// ---------------------------------------------------------------------------
__global__ void split_w_kernel(
    const float* p0, const float* p1, const float* p2, const float* p3,
    const float* p4, const float* p5, const float* p6, const float* p7,
    const float* p8, const float* p9, const float* p10) {
    const float* srcs[11] = {p0, p1, p2, p3, p4, p5, p6, p7, p8, p9, p10};
    const int KK[11]  = {256, 256, 256, 64, 256, 256, 256, 256, 256, 256, 256};
    const int NN[11]  = {256, 256, 64, 256, 256, 256, 256, 256, 256, 256, 256};
    const int NC[11]  = {8, 8, 4, 8, 8, 8, 8, 8, 8, 8, 8};
    const int w = blockIdx.y;
    const int i = blockIdx.x * 256 + threadIdx.x;
    const int K = KK[w], N = NN[w], ncblk = NC[w];
    const int total = (K / 16) * ncblk * 256;
    if (i >= total) return;
    const int kb = i / (ncblk * 256);
    const int rem = i % (ncblk * 256);
    const int cblk = rem >> 8;
    const int j = rem & 255;
    const int r = j >> 7, lane = (j >> 2) & 31, nt = j & 3;
    const int gg = lane >> 2, tt = lane & 3;
    const int k0 = kb * 16 + r * 8 + tt * 2;
    const int n  = cblk * 32 + nt * 8 + gg;
    const float* W = srcs[w];
    float v0 = (n < N && k0 < K)     ? W[(size_t)k0 * N + n]       : 0.f;
    float v1 = (n < N && k0 + 1 < K) ? W[(size_t)(k0 + 1) * N + n] : 0.f;
    __half h0, l0, h1, l1;
    h_split(v0, h0, l0); h_split(v1, h1, l1);
    const size_t o = (size_t)i * 2;
    __half* hi = g_Wsp + (size_t)(2 * w) * 65536;
    __half* lo = g_Wsp + (size_t)(2 * w + 1) * 65536;
    *reinterpret_cast<__half2*>(hi + o) = __halves2half2(h0, h1);
    *reinterpret_cast<__half2*>(lo + o) = __halves2half2(l0, l1);
}

__global__ void split_pair_kernel(const float* __restrict__ src,
                                  __half* __restrict__ hi, __half* __restrict__ lo,
                                  int n4) {
    int i = blockIdx.x * 256 + threadIdx.x;
    if (i < n4) {
        float4 v = reinterpret_cast<const float4*>(src)[i];
        __half h0, l0, h1, l1, h2, l2, h3, l3;
        h_split(v.x, h0, l0); h_split(v.y, h1, l1);
        h_split(v.z, h2, l2); h_split(v.w, h3, l3);
        reinterpret_cast<__half2*>(hi)[i * 2]     = __halves2half2(h0, h1);
        reinterpret_cast<__half2*>(hi)[i * 2 + 1] = __halves2half2(h2, h3);
        reinterpret_cast<__half2*>(lo)[i * 2]     = __halves2half2(l0, l1);
        reinterpret_cast<__half2*>(lo)[i * 2 + 1] = __halves2half2(l2, l3);
    }
}

__global__ void zero_agg_kernel(int n4) {
    int i = blockIdx.x * 256 + threadIdx.x;
    if (i < n4) reinterpret_cast<float4*>(g_agg)[i] = make_float4(0.f, 0.f, 0.f, 0.f);
}

__global__ void wr_kernel(const float* __restrict__ W1, const float* __restrict__ W2) {
    int c = threadIdx.x;
    #pragma unroll
    for (int k = 0; k < NRAD; k++) {
        float v = 0.f;
        #pragma unroll
        for (int j = 0; j < BAS; j++) v += W1[k * BAS + j] * W2[j * H + c];
        g_Wr[k * H + c] = v;
    }
}

__global__ void __launch_bounds__(256) rbfe_kernel(
    const float* __restrict__ rbf, float* __restrict__ out, int E) {
    __shared__ float srbf[64 * NRAD];
    const int tid = threadIdx.x;
    const int e0 = blockIdx.x * 64;
    float w[NRAD];
    #pragma unroll
    for (int k = 0; k < NRAD; k++) w[k] = g_Wr[k * H + tid];
    for (int i = tid; i < 64 * NRAD; i += 256) {
        int e = e0 + i / NRAD;
        srbf[i] = (e < E) ? rbf[(size_t)e * NRAD + (i % NRAD)] : 0.f;
    }
    __syncthreads();
    for (int r = 0; r < 64; r++) {
        int e = e0 + r;
        if (e >= E) break;
        float v = 0.f;
        #pragma unroll
        for (int k = 0; k < NRAD; k++) v += w[k] * srbf[r * NRAD + k];
        out[(size_t)e * H + tid] = v;
    }
}

// ---------------------------------------------------------------------------
// Triplet scatter (red.global.add.v4)
// ---------------------------------------------------------------------------
#define SC_TRI 32
__global__ void __launch_bounds__(512) scatter_v4_kernel(
    const float* __restrict__ sbf, const int* __restrict__ idx_kj,
    const int* __restrict__ idx_ji, const float* __restrict__ W1,
    const float* __restrict__ W2, int T) {
    __shared__ float W1s[SBF_DIM * BAS];
    __shared__ float W2s[BAS * INTC];
    __shared__ float sbfs[SC_TRI][SBF_DIM + 2];
    __shared__ float bs[SC_TRI][BAS];

    const int tid = threadIdx.x;
    for (int i = tid; i < SBF_DIM * BAS; i += 512) W1s[i] = W1[i];
    for (int i = tid; i < BAS * INTC; i += 512) W2s[i] = W2[i];

    const int t = tid >> 4;
    const int l = tid & 15;
    const long tri = (long)blockIdx.x * SC_TRI + t;
    const bool valid = tri < (long)T;

    if (valid) {
        #pragma unroll
        for (int i = l; i < SBF_DIM; i += 16) sbfs[t][i] = sbf[tri * SBF_DIM + i];
    }
    __syncthreads();

    if (valid && l < BAS) {
        float b = 0.f;
        #pragma unroll
        for (int j = 0; j < SBF_DIM; j++) b += sbfs[t][j] * W1s[j * BAS + l];
        bs[t][l] = b;
    }
    __syncthreads();

    if (valid) {
        const int c0 = l * 4;
        float s0 = 0.f, s1 = 0.f, s2 = 0.f, s3 = 0.f;
        #pragma unroll
        for (int k = 0; k < BAS; k++) {
            const float bk = bs[t][k];
            const float* w = &W2s[k * INTC + c0];
            s0 += bk * w[0]; s1 += bk * w[1]; s2 += bk * w[2]; s3 += bk * w[3];
        }
        const int kj = idx_kj[tri];
        const int ji = idx_ji[tri];
        const float4 d = __ldg(reinterpret_cast<const float4*>(&g_down[(size_t)kj * INTC + c0]));
        s0 *= d.x; s1 *= d.y; s2 *= d.z; s3 *= d.w;
        float* dst = &g_agg[(size_t)ji * INTC + c0];
        asm volatile("red.global.add.v4.f32 [%0], {%1,%2,%3,%4};"
                     :: "l"(dst), "f"(s0), "f"(s1), "f"(s2), "f"(s3) : "memory");
    }
}

// ---------------------------------------------------------------------------
// Host orchestration
// ---------------------------------------------------------------------------
struct Pair { __half* h; __half* l; };

static inline void launch_gemm(Pair A, const __half* bh, const __half* bl,
                               const float* bias, const float* mul, const float* addF,
                               Pair addP, float* Cf, Pair Cp,
                               int M, int N, int K, int ncblk) {
    dim3 grid((M + BM - 1) / BM, N / BN);
    gemm_f16x2<<<grid, 256, SMEM_BYTES>>>(A.h, A.l, bh, bl, bias, mul, addF,
                                          addP.h, addP.l, Cf, Cp.h, Cp.l,
                                          M, N, K, ncblk);
}

extern "C" void kernel_launch(void* const* d_in, const int* in_sizes, int n_in,
                              void* d_out, int out_size) {
    const float* x      = (const float*)d_in[0];
    const float* rbf    = (const float*)d_in[1];
    const float* sbf    = (const float*)d_in[2];
    const int*   idx_kj = (const int*)d_in[3];
    const int*   idx_ji = (const int*)d_in[4];
    const float* W_rbf1 = (const float*)d_in[5];
    const float* W_rbf2 = (const float*)d_in[6];
    const float* W_sbf1 = (const float*)d_in[7];
    const float* W_sbf2 = (const float*)d_in[8];
    const float* W_kj   = (const float*)d_in[9];
    const float* b_kj   = (const float*)d_in[10];
    const float* W_ji   = (const float*)d_in[11];
    const float* b_ji   = (const float*)d_in[12];
    const float* W_down = (const float*)d_in[13];
    const float* W_up   = (const float*)d_in[14];
    const float* rb_W1  = (const float*)d_in[15];
    const float* rb_b1  = (const float*)d_in[16];
    const float* rb_W2  = (const float*)d_in[17];
    const float* rb_b2  = (const float*)d_in[18];
    const float* W_lin  = (const float*)d_in[19];
    const float* b_lin  = (const float*)d_in[20];
    const float* ra_W1  = (const float*)d_in[21];
    const float* ra_b1  = (const float*)d_in[22];
    const float* ra_W2  = (const float*)d_in[23];
    const float* ra_b2  = (const float*)d_in[24];

    const int E = in_sizes[0] / H;
    const int T = in_sizes[3];
    float* out = (float*)d_out;

    cudaFuncSetAttribute(gemm_f16x2, cudaFuncAttributeMaxDynamicSharedMemorySize, SMEM_BYTES);

    float *buf0, *buf1, *down, *agg;
    __half *P0h, *P0l, *P1h, *P1l, *P2h, *P2l, *aggh, *aggl, *wsp;
    cudaGetSymbolAddress((void**)&buf0, g_buf0);
    cudaGetSymbolAddress((void**)&buf1, g_buf1);
    cudaGetSymbolAddress((void**)&down, g_down);
    cudaGetSymbolAddress((void**)&agg,  g_agg);
    cudaGetSymbolAddress((void**)&P0h, g_P0h); cudaGetSymbolAddress((void**)&P0l, g_P0l);
    cudaGetSymbolAddress((void**)&P1h, g_P1h); cudaGetSymbolAddress((void**)&P1l, g_P1l);
    cudaGetSymbolAddress((void**)&P2h, g_P2h); cudaGetSymbolAddress((void**)&P2l, g_P2l);
    cudaGetSymbolAddress((void**)&aggh, g_aggh); cudaGetSymbolAddress((void**)&aggl, g_aggl);
    cudaGetSymbolAddress((void**)&wsp, g_Wsp);
    #define WHI(w) (wsp + (size_t)(2 * (w)) * 65536)
    #define WLO(w) (wsp + (size_t)(2 * (w) + 1) * 65536)

    const Pair P0{P0h, P0l}, P1{P1h, P1l}, P2{P2h, P2l}, Pagg{aggh, aggl};
    const Pair NOP{nullptr, nullptr};

    // L1 split_w  L2 wr  L3 split x  L4 = BIG GEMM (ncu capture slot)
    split_w_kernel<<<dim3(128, 11), 256>>>(
        W_ji, W_kj, W_down, W_up, rb_W1, rb_W2, W_lin, ra_W1, ra_W2,
        ra_W1 + (size_t)H * H, ra_W2 + (size_t)H * H);
    wr_kernel<<<1, 256>>>(W_rbf1, W_rbf2);
    split_pair_kernel<<<((E * H / 4) + 255) / 256, 256>>>(x, P0h, P0l, E * H / 4);

    // L4: x_ji
    launch_gemm(P0, WHI(0), WLO(0), b_ji, nullptr, nullptr, NOP, buf0, NOP, E, H, H, 8);
    rbfe_kernel<<<(E + 63) / 64, 256>>>(rbf, buf1, E);
    zero_agg_kernel<<<(E * INTC / 4 + 255) / 256, 256>>>(E * INTC / 4);
    launch_gemm(P0, WHI(1), WLO(1), b_kj, buf1, nullptr, NOP, nullptr, P1, E, H, H, 8);
    launch_gemm(P1, WHI(2), WLO(2), nullptr, nullptr, nullptr, NOP, down, NOP, E, INTC, H, 4);

    scatter_v4_kernel<<<(T + SC_TRI - 1) / SC_TRI, 512>>>(sbf, idx_kj, idx_ji,
                                                          W_sbf1, W_sbf2, T);
    split_pair_kernel<<<((E * INTC / 4) + 255) / 256, 256>>>(agg, aggh, aggl, E * INTC / 4);

    launch_gemm(Pagg, WHI(3), WLO(3), nullptr, nullptr, buf0, NOP, nullptr, P2, E, H, INTC, 8);
    launch_gemm(P2, WHI(4), WLO(4), rb_b1, nullptr, nullptr, NOP, nullptr, P1, E, H, H, 8);
    launch_gemm(P1, WHI(5), WLO(5), rb_b2, nullptr, nullptr, P2, nullptr, P0, E, H, H, 8);
    launch_gemm(P0, WHI(6), WLO(6), b_lin, nullptr, x, NOP, nullptr, P2, E, H, H, 8);
    launch_gemm(P2, WHI(7), WLO(7), ra_b1, nullptr, nullptr, NOP, nullptr, P1, E, H, H, 8);
    launch_gemm(P1, WHI(8), WLO(8), ra_b2, nullptr, nullptr, P2, nullptr, P0, E, H, H, 8);
    launch_gemm(P0, WHI(9), WLO(9), ra_b1 + H, nullptr, nullptr, NOP, nullptr, P1, E, H, H, 8);
    launch_gemm(P1, WHI(10), WLO(10), ra_b2 + H, nullptr, nullptr, P0, out, NOP, E, H, H, 8);
}

// round 9
// speedup vs baseline: 2.8725x; 1.2370x over previous
#include <cuda_runtime.h>
#include <cuda_fp16.h>
#include <cstdint>

// ---------------------------------------------------------------------------
// InteractionPPBlock (DimeNet++) — round 9: fully-unrolled templated mainloop,
// term-major mma ordering (dependency distance 8), 2 CTAs/SM
// ---------------------------------------------------------------------------

#define H 256
#define INTC 64
#define SBF_DIM 42
#define NRAD 6
#define BAS 8

#define MAXE 200704
#define MAXE_H ((size_t)MAXE * H)
#define MAXE_I ((size_t)MAXE * INTC)

__device__ float g_buf0[MAXE_H];
__device__ float g_buf1[MAXE_H];
__device__ float g_down[MAXE_I];
__device__ float g_agg[MAXE_I];
__device__ float g_Wr[NRAD * H];
__device__ __half g_P0h[MAXE_H], g_P0l[MAXE_H];
__device__ __half g_P1h[MAXE_H], g_P1l[MAXE_H];
__device__ __half g_P2h[MAXE_H], g_P2l[MAXE_H];
__device__ __half g_aggh[MAXE_I], g_aggl[MAXE_I];
__device__ __half g_Wsp[22 * 65536];

__device__ __forceinline__ float silu(float v) {
    return v / (1.0f + __expf(-v));
}
__device__ __forceinline__ void h_split(float v, __half& h, __half& l) {
    h = __float2half_rn(v);
    l = __float2half_rn(v - __half2float(h));
}

__device__ __forceinline__ void mma_f16(float* d, const uint32_t* a, const uint32_t* b) {
    asm volatile(
        "mma.sync.aligned.m16n8k16.row.col.f32.f16.f16.f32 "
        "{%0,%1,%2,%3},{%4,%5,%6,%7},{%8,%9},{%0,%1,%2,%3};\n"
        : "+f"(d[0]), "+f"(d[1]), "+f"(d[2]), "+f"(d[3])
        : "r"(a[0]), "r"(a[1]), "r"(a[2]), "r"(a[3]), "r"(b[0]), "r"(b[1]));
}
__device__ __forceinline__ void ldsm_x4(uint32_t* r, uint32_t addr) {
    asm volatile("ldmatrix.sync.aligned.m8n8.x4.shared.b16 {%0,%1,%2,%3}, [%4];"
                 : "=r"(r[0]), "=r"(r[1]), "=r"(r[2]), "=r"(r[3]) : "r"(addr));
}

__device__ __forceinline__ uint32_t smem_u32(const void* p) {
    uint32_t a;
    asm("{ .reg .u64 t; cvta.to.shared.u64 t, %1; cvt.u32.u64 %0, t; }" : "=r"(a) : "l"(p));
    return a;
}
__device__ __forceinline__ void cp_async16(uint32_t dst, const void* src, int szr) {
    asm volatile("cp.async.cg.shared.global [%0], [%1], 16, %2;"
                 :: "r"(dst), "l"(src), "r"(szr) : "memory");
}
#define CP_COMMIT() asm volatile("cp.async.commit_group;" ::: "memory")
#define CP_WAIT(n)  asm volatile("cp.async.wait_group %0;" :: "n"(n) : "memory")

// ---------------------------------------------------------------------------
// GEMM: BM=128, BN=64, BK=16, 256 threads (8 warps 4x2), 4 stages
// stage (16384 B): Ahi [0,6144) Alo [6144,12288) Bhi [12288,14336) Blo [14336,16384)
// ---------------------------------------------------------------------------
#define BM 128
#define BN 64
#define STAGES 4
#define STG 16384
#define SMEM_BYTES (STAGES * STG)

template <int NK, int NCBLK>
__global__ void __launch_bounds__(256, 2) gemm_f16x2(
    const __half* __restrict__ Ah, const __half* __restrict__ Al,
    const __half* __restrict__ Bh, const __half* __restrict__ Bl,
    const float* __restrict__ bias, const float* __restrict__ mul,
    const float* __restrict__ addF,
    const __half* __restrict__ addH, const __half* __restrict__ addL,
    float* __restrict__ Cf, __half* __restrict__ Chi, __half* __restrict__ Clo,
    int M, int N) {

    constexpr int K = NK * 16;
    extern __shared__ char smem_raw[];
    char* bp = smem_raw;
    const uint32_t s0 = smem_u32(smem_raw);

    const int tid  = threadIdx.x;
    const int wid  = tid >> 5;
    const int lane = tid & 31;
    const int g    = lane >> 2;
    const int t    = lane & 3;
    const int wy   = wid >> 1;
    const int wx   = wid & 1;

    const int rowBase = blockIdx.x * BM;
    const int colBase = blockIdx.y * BN;
    const int cblk0   = colBase >> 5;

    // hoisted cp.async addressing
    const int ar = tid >> 1, ac = tid & 1;
    const int gr = rowBase + ar;
    const bool aV = gr < M;
    const __half* aSrcH = Ah + (size_t)(aV ? gr : 0) * K + ac * 8;
    const __half* aSrcL = Al + (size_t)(aV ? gr : 0) * K + ac * 8;
    const uint32_t aDstH = s0 + (uint32_t)(ar * 48 + ac * 16);
    const uint32_t aDstL = aDstH + 6144u;

    const int bj = tid & 127;
    const int cblkL = bj >> 6, brr = (bj >> 5) & 1, bln = bj & 31;
    const __half* bSrc = ((tid < 128) ? Bh : Bl)
        + ((size_t)((cblk0 + cblkL) * 2 + brr) * 32 + bln) * 8;
    const uint32_t bDst = s0 + 12288u + (tid < 128 ? 0u : 2048u) + (uint32_t)bj * 16;
    constexpr int bStep = NCBLK * 512;

    const uint32_t lds_a_off =
        (uint32_t)(((lane & 7) + ((lane >> 3) & 1) * 8) * 48 + ((lane >> 4) & 1) * 16);

    float acc[2][4][4];
    #pragma unroll
    for (int i = 0; i < 2; i++)
        #pragma unroll
        for (int j = 0; j < 4; j++)
            #pragma unroll
            for (int r = 0; r < 4; r++) acc[i][j][r] = 0.f;

    #pragma unroll
    for (int s = 0; s < STAGES - 1; s++) {
        if (s < NK) {
            cp_async16(aDstH + s * STG, aSrcH + s * 16, aV ? 16 : 0);
            cp_async16(aDstL + s * STG, aSrcL + s * 16, aV ? 16 : 0);
            cp_async16(bDst + s * STG, bSrc + (size_t)s * bStep, 16);
        }
        CP_COMMIT();
    }

    #pragma unroll
    for (int it = 0; it < NK; ++it) {
        constexpr int dummy = 0; (void)dummy;
        const int pend = NK - 1 - it;
        if (pend >= 2)      CP_WAIT(2);
        else if (pend == 1) CP_WAIT(1);
        else                CP_WAIT(0);
        __syncthreads();

        const int nx = it + STAGES - 1;
        if (nx < NK) {
            const uint32_t so = (uint32_t)(nx % STAGES) * STG;
            cp_async16(aDstH + so, aSrcH + nx * 16, aV ? 16 : 0);
            cp_async16(aDstL + so, aSrcL + nx * 16, aV ? 16 : 0);
            cp_async16(bDst + so, bSrc + (size_t)nx * bStep, 16);
            CP_COMMIT();
        }

        const uint32_t sb = (uint32_t)(it % STAGES) * STG;

        // ---- load ALL fragments for this tile ----
        uint4 vh0 = *reinterpret_cast<uint4*>(bp + sb + 12288 + ((wx * 2 + 0) * 32 + lane) * 16);
        uint4 vh1 = *reinterpret_cast<uint4*>(bp + sb + 12288 + ((wx * 2 + 1) * 32 + lane) * 16);
        uint4 vl0 = *reinterpret_cast<uint4*>(bp + sb + 14336 + ((wx * 2 + 0) * 32 + lane) * 16);
        uint4 vl1 = *reinterpret_cast<uint4*>(bp + sb + 14336 + ((wx * 2 + 1) * 32 + lane) * 16);
        uint32_t bh[4][2], bl[4][2];
        bh[0][0] = vh0.x; bh[1][0] = vh0.y; bh[2][0] = vh0.z; bh[3][0] = vh0.w;
        bh[0][1] = vh1.x; bh[1][1] = vh1.y; bh[2][1] = vh1.z; bh[3][1] = vh1.w;
        bl[0][0] = vl0.x; bl[1][0] = vl0.y; bl[2][0] = vl0.z; bl[3][0] = vl0.w;
        bl[0][1] = vl1.x; bl[1][1] = vl1.y; bl[2][1] = vl1.z; bl[3][1] = vl1.w;

        uint32_t ah[2][4], al[2][4];
        #pragma unroll
        for (int mt = 0; mt < 2; mt++) {
            const int m0 = wy * 32 + mt * 16;
            ldsm_x4(ah[mt], s0 + sb + (uint32_t)(m0 * 48) + lds_a_off);
            ldsm_x4(al[mt], s0 + sb + 6144u + (uint32_t)(m0 * 48) + lds_a_off);
        }

        // ---- term-major mma: dependent pairs 8 apart ----
        #pragma unroll
        for (int mt = 0; mt < 2; mt++)
            #pragma unroll
            for (int nt = 0; nt < 4; nt++)
                mma_f16(acc[mt][nt], al[mt], bh[nt]);
        #pragma unroll
        for (int mt = 0; mt < 2; mt++)
            #pragma unroll
            for (int nt = 0; nt < 4; nt++)
                mma_f16(acc[mt][nt], ah[mt], bl[nt]);
        #pragma unroll
        for (int mt = 0; mt < 2; mt++)
            #pragma unroll
            for (int nt = 0; nt < 4; nt++)
                mma_f16(acc[mt][nt], ah[mt], bh[nt]);
    }

    // epilogue
    #pragma unroll
    for (int mt = 0; mt < 2; mt++) {
        #pragma unroll
        for (int nt = 0; nt < 4; nt++) {
            const int c0 = colBase + wx * 32 + nt * 8 + 2 * t;
            if (c0 >= N) continue;
            #pragma unroll
            for (int half = 0; half < 2; half++) {
                const int row = rowBase + wy * 32 + mt * 16 + g + 8 * half;
                if (row >= M) continue;
                const size_t idx = (size_t)row * N + c0;
                float v0 = acc[mt][nt][half * 2];
                float v1 = acc[mt][nt][half * 2 + 1];
                if (bias) { v0 += bias[c0]; v1 += bias[c0 + 1]; }
                v0 = silu(v0); v1 = silu(v1);
                if (mul)  { v0 *= mul[idx];  v1 *= mul[idx + 1]; }
                if (addF) { v0 += addF[idx]; v1 += addF[idx + 1]; }
                if (addH) {
                    v0 += __half2float(addH[idx]) + __half2float(addL[idx]);
                    v1 += __half2float(addH[idx + 1]) + __half2float(addL[idx + 1]);
                }
                if (Cf) { Cf[idx] = v0; Cf[idx + 1] = v1; }
                if (Chi) {
                    __half h0, l0, h1, l1;
                    h_split(v0, h0, l0); h_split(v1, h1, l1);
                    *reinterpret_cast<__half2*>(Chi + idx) = __halves2half2(h0, h1);
                    *reinterpret_cast<__half2*>(Clo + idx) = __halves2half2(l0, l1);
                }
            }
        }
    }
}

// ---------------------------------------------------------------------------
// Prep kernels
// ---------------------------------------------------------------------------
__global__ void split_w_kernel(
    const float* p0, const float* p1, const float* p2, const float* p3,
    const float* p4, const float* p5, const float* p6, const float* p7,
    const float* p8, const float* p9, const float* p10) {
    const float* srcs[11] = {p0, p1, p2, p3, p4, p5, p6, p7, p8, p9, p10};
    const int KK[11]  = {256, 256, 256, 64, 256, 256, 256, 256, 256, 256, 256};
    const int NN[11]  = {256, 256, 64, 256, 256, 256, 256, 256, 256, 256, 256};
    const int NC[11]  = {8, 8, 4, 8, 8, 8, 8, 8, 8, 8, 8};
    const int w = blockIdx.y;
    const int i = blockIdx.x * 256 + threadIdx.x;
    const int K = KK[w], N = NN[w], ncblk = NC[w];
    const int total = (K / 16) * ncblk * 256;
    if (i >= total) return;
    const int kb = i / (ncblk * 256);
    const int rem = i % (ncblk * 256);
    const int cblk = rem >> 8;
    const int j = rem & 255;
    const int r = j >> 7, lane = (j >> 2) & 31, nt = j & 3;
    const int gg = lane >> 2, tt = lane & 3;
    const int k0 = kb * 16 + r * 8 + tt * 2;
    const int n  = cblk * 32 + nt * 8 + gg;
    const float* W = srcs[w];
    float v0 = (n < N && k0 < K)     ? W[(size_t)k0 * N + n]       : 0.f;
    float v1 = (n < N && k0 + 1 < K) ? W[(size_t)(k0 + 1) * N + n] : 0.f;
    __half h0, l0, h1, l1;
    h_split(v0, h0, l0); h_split(v1, h1, l1);
    const size_t o = (size_t)i * 2;
    __half* hi = g_Wsp + (size_t)(2 * w) * 65536;
    __half* lo = g_Wsp + (size_t)(2 * w + 1) * 65536;
    *reinterpret_cast<__half2*>(hi + o) = __halves2half2(h0, h1);
    *reinterpret_cast<__half2*>(lo + o) = __halves2half2(l0, l1);
}

__global__ void split_pair_kernel(const float* __restrict__ src,
                                  __half* __restrict__ hi, __half* __restrict__ lo,
                                  int n4) {
    int i = blockIdx.x * 256 + threadIdx.x;
    if (i < n4) {
        float4 v = reinterpret_cast<const float4*>(src)[i];
        __half h0, l0, h1, l1, h2, l2, h3, l3;
        h_split(v.x, h0, l0); h_split(v.y, h1, l1);
        h_split(v.z, h2, l2); h_split(v.w, h3, l3);
        reinterpret_cast<__half2*>(hi)[i * 2]     = __halves2half2(h0, h1);
        reinterpret_cast<__half2*>(hi)[i * 2 + 1] = __halves2half2(h2, h3);
        reinterpret_cast<__half2*>(lo)[i * 2]     = __halves2half2(l0, l1);
        reinterpret_cast<__half2*>(lo)[i * 2 + 1] = __halves2half2(l2, l3);
    }
}

__global__ void zero_agg_kernel(int n4) {
    int i = blockIdx.x * 256 + threadIdx.x;
    if (i < n4) reinterpret_cast<float4*>(g_agg)[i] = make_float4(0.f, 0.f, 0.f, 0.f);
}

__global__ void wr_kernel(const float* __restrict__ W1, const float* __restrict__ W2) {
    int c = threadIdx.x;
    #pragma unroll
    for (int k = 0; k < NRAD; k++) {
        float v = 0.f;
        #pragma unroll
        for (int j = 0; j < BAS; j++) v += W1[k * BAS + j] * W2[j * H + c];
        g_Wr[k * H + c] = v;
    }
}

__global__ void __launch_bounds__(256) rbfe_kernel(
    const float* __restrict__ rbf, float* __restrict__ out, int E) {
    __shared__ float srbf[64 * NRAD];
    const int tid = threadIdx.x;
    const int e0 = blockIdx.x * 64;
    float w[NRAD];
    #pragma unroll
    for (int k = 0; k < NRAD; k++) w[k] = g_Wr[k * H + tid];
    for (int i = tid; i < 64 * NRAD; i += 256) {
        int e = e0 + i / NRAD;
        srbf[i] = (e < E) ? rbf[(size_t)e * NRAD + (i % NRAD)] : 0.f;
    }
    __syncthreads();
    for (int r = 0; r < 64; r++) {
        int e = e0 + r;
        if (e >= E) break;
        float v = 0.f;
        #pragma unroll
        for (int k = 0; k < NRAD; k++) v += w[k] * srbf[r * NRAD + k];
        out[(size_t)e * H + tid] = v;
    }
}

// ---------------------------------------------------------------------------
// Triplet scatter
// ---------------------------------------------------------------------------
#define SC_TRI 32
__global__ void __launch_bounds__(512) scatter_v4_kernel(
    const float* __restrict__ sbf, const int* __restrict__ idx_kj,
    const int* __restrict__ idx_ji, const float* __restrict__ W1,
    const float* __restrict__ W2, int T) {
    __shared__ float W1s[SBF_DIM * BAS];
    __shared__ float W2s[BAS * INTC];
    __shared__ float sbfs[SC_TRI][SBF_DIM + 2];
    __shared__ float bs[SC_TRI][BAS];

    const int tid = threadIdx.x;
    for (int i = tid; i < SBF_DIM * BAS; i += 512) W1s[i] = W1[i];
    for (int i = tid; i < BAS * INTC; i += 512) W2s[i] = W2[i];

    const int t = tid >> 4;
    const int l = tid & 15;
    const long tri = (long)blockIdx.x * SC_TRI + t;
    const bool valid = tri < (long)T;

    if (valid) {
        #pragma unroll
        for (int i = l; i < SBF_DIM; i += 16) sbfs[t][i] = sbf[tri * SBF_DIM + i];
    }
    __syncthreads();

    if (valid && l < BAS) {
        float b = 0.f;
        #pragma unroll
        for (int j = 0; j < SBF_DIM; j++) b += sbfs[t][j] * W1s[j * BAS + l];
        bs[t][l] = b;
    }
    __syncthreads();

    if (valid) {
        const int c0 = l * 4;
        float s0 = 0.f, s1 = 0.f, s2 = 0.f, s3 = 0.f;
        #pragma unroll
        for (int k = 0; k < BAS; k++) {
            const float bk = bs[t][k];
            const float* w = &W2s[k * INTC + c0];
            s0 += bk * w[0]; s1 += bk * w[1]; s2 += bk * w[2]; s3 += bk * w[3];
        }
        const int kj = idx_kj[tri];
        const int ji = idx_ji[tri];
        const float4 d = __ldg(reinterpret_cast<const float4*>(&g_down[(size_t)kj * INTC + c0]));
        s0 *= d.x; s1 *= d.y; s2 *= d.z; s3 *= d.w;
        float* dst = &g_agg[(size_t)ji * INTC + c0];
        asm volatile("red.global.add.v4.f32 [%0], {%1,%2,%3,%4};"
                     :: "l"(dst), "f"(s0), "f"(s1), "f"(s2), "f"(s3) : "memory");
    }
}

// ---------------------------------------------------------------------------
// Host orchestration
// ---------------------------------------------------------------------------
struct Pair { __half* h; __half* l; };

static inline void launch_gemm(Pair A, const __half* bh, const __half* bl,
                               const float* bias, const float* mul, const float* addF,
                               Pair addP, float* Cf, Pair Cp,
                               int M, int N, int K, int ncblk) {
    dim3 grid((M + BM - 1) / BM, N / BN);
    if (K == 256 && ncblk == 8)
        gemm_f16x2<16, 8><<<grid, 256, SMEM_BYTES>>>(A.h, A.l, bh, bl, bias, mul, addF,
                                                     addP.h, addP.l, Cf, Cp.h, Cp.l, M, N);
    else if (K == 256)
        gemm_f16x2<16, 4><<<grid, 256, SMEM_BYTES>>>(A.h, A.l, bh, bl, bias, mul, addF,
                                                     addP.h, addP.l, Cf, Cp.h, Cp.l, M, N);
    else
        gemm_f16x2<4, 8><<<grid, 256, SMEM_BYTES>>>(A.h, A.l, bh, bl, bias, mul, addF,
                                                    addP.h, addP.l, Cf, Cp.h, Cp.l, M, N);
}

extern "C" void kernel_launch(void* const* d_in, const int* in_sizes, int n_in,
                              void* d_out, int out_size) {
    const float* x      = (const float*)d_in[0];
    const float* rbf    = (const float*)d_in[1];
    const float* sbf    = (const float*)d_in[2];
    const int*   idx_kj = (const int*)d_in[3];
    const int*   idx_ji = (const int*)d_in[4];
    const float* W_rbf1 = (const float*)d_in[5];
    const float* W_rbf2 = (const float*)d_in[6];
    const float* W_sbf1 = (const float*)d_in[7];
    const float* W_sbf2 = (const float*)d_in[8];
    const float* W_kj   = (const float*)d_in[9];
    const float* b_kj   = (const float*)d_in[10];
    const float* W_ji   = (const float*)d_in[11];
    const float* b_ji   = (const float*)d_in[12];
    const float* W_down = (const float*)d_in[13];
    const float* W_up   = (const float*)d_in[14];
    const float* rb_W1  = (const float*)d_in[15];
    const float* rb_b1  = (const float*)d_in[16];
    const float* rb_W2  = (const float*)d_in[17];
    const float* rb_b2  = (const float*)d_in[18];
    const float* W_lin  = (const float*)d_in[19];
    const float* b_lin  = (const float*)d_in[20];
    const float* ra_W1  = (const float*)d_in[21];
    const float* ra_b1  = (const float*)d_in[22];
    const float* ra_W2  = (const float*)d_in[23];
    const float* ra_b2  = (const float*)d_in[24];

    const int E = in_sizes[0] / H;
    const int T = in_sizes[3];
    float* out = (float*)d_out;

    cudaFuncSetAttribute(gemm_f16x2<16, 8>, cudaFuncAttributeMaxDynamicSharedMemorySize, SMEM_BYTES);
    cudaFuncSetAttribute(gemm_f16x2<16, 4>, cudaFuncAttributeMaxDynamicSharedMemorySize, SMEM_BYTES);
    cudaFuncSetAttribute(gemm_f16x2<4, 8>,  cudaFuncAttributeMaxDynamicSharedMemorySize, SMEM_BYTES);

    float *buf0, *buf1, *down, *agg;
    __half *P0h, *P0l, *P1h, *P1l, *P2h, *P2l, *aggh, *aggl, *wsp;
    cudaGetSymbolAddress((void**)&buf0, g_buf0);
    cudaGetSymbolAddress((void**)&buf1, g_buf1);
    cudaGetSymbolAddress((void**)&down, g_down);
    cudaGetSymbolAddress((void**)&agg,  g_agg);
    cudaGetSymbolAddress((void**)&P0h, g_P0h); cudaGetSymbolAddress((void**)&P0l, g_P0l);
    cudaGetSymbolAddress((void**)&P1h, g_P1h); cudaGetSymbolAddress((void**)&P1l, g_P1l);
    cudaGetSymbolAddress((void**)&P2h, g_P2h); cudaGetSymbolAddress((void**)&P2l, g_P2l);
    cudaGetSymbolAddress((void**)&aggh, g_aggh); cudaGetSymbolAddress((void**)&aggl, g_aggl);
    cudaGetSymbolAddress((void**)&wsp, g_Wsp);
    #define WHI(w) (wsp + (size_t)(2 * (w)) * 65536)
    #define WLO(w) (wsp + (size_t)(2 * (w) + 1) * 65536)

    const Pair P0{P0h, P0l}, P1{P1h, P1l}, P2{P2h, P2l}, Pagg{aggh, aggl};
    const Pair NOP{nullptr, nullptr};

    split_w_kernel<<<dim3(128, 11), 256>>>(
        W_ji, W_kj, W_down, W_up, rb_W1, rb_W2, W_lin, ra_W1, ra_W2,
        ra_W1 + (size_t)H * H, ra_W2 + (size_t)H * H);
    wr_kernel<<<1, 256>>>(W_rbf1, W_rbf2);
    split_pair_kernel<<<((E * H / 4) + 255) / 256, 256>>>(x, P0h, P0l, E * H / 4);

    // L4: big GEMM (ncu slot)
    launch_gemm(P0, WHI(0), WLO(0), b_ji, nullptr, nullptr, NOP, buf0, NOP, E, H, H, 8);
    rbfe_kernel<<<(E + 63) / 64, 256>>>(rbf, buf1, E);
    zero_agg_kernel<<<(E * INTC / 4 + 255) / 256, 256>>>(E * INTC / 4);
    launch_gemm(P0, WHI(1), WLO(1), b_kj, buf1, nullptr, NOP, nullptr, P1, E, H, H, 8);
    launch_gemm(P1, WHI(2), WLO(2), nullptr, nullptr, nullptr, NOP, down, NOP, E, INTC, H, 4);

    scatter_v4_kernel<<<(T + SC_TRI - 1) / SC_TRI, 512>>>(sbf, idx_kj, idx_ji,
                                                          W_sbf1, W_sbf2, T);
    split_pair_kernel<<<((E * INTC / 4) + 255) / 256, 256>>>(agg, aggh, aggl, E * INTC / 4);

    launch_gemm(Pagg, WHI(3), WLO(3), nullptr, nullptr, buf0, NOP, nullptr, P2, E, H, INTC, 8);
    launch_gemm(P2, WHI(4), WLO(4), rb_b1, nullptr, nullptr, NOP, nullptr, P1, E, H, H, 8);
    launch_gemm(P1, WHI(5), WLO(5), rb_b2, nullptr, nullptr, P2, nullptr, P0, E, H, H, 8);
    launch_gemm(P0, WHI(6), WLO(6), b_lin, nullptr, x, NOP, nullptr, P2, E, H, H, 8);
    launch_gemm(P2, WHI(7), WLO(7), ra_b1, nullptr, nullptr, NOP, nullptr, P1, E, H, H, 8);
    launch_gemm(P1, WHI(8), WLO(8), ra_b2, nullptr, nullptr, P2, nullptr, P0, E, H, H, 8);
    launch_gemm(P0, WHI(9), WLO(9), ra_b1 + H, nullptr, nullptr, NOP, nullptr, P1, E, H, H, 8);
    launch_gemm(P1, WHI(10), WLO(10), ra_b2 + H, nullptr, nullptr, P0, out, NOP, E, H, H, 8);
}

// round 10
// speedup vs baseline: 2.8915x; 1.0066x over previous
#include <cuda_runtime.h>
#include <cuda_fp16.h>
#include <cstdint>

// ---------------------------------------------------------------------------
// InteractionPPBlock (DimeNet++) — round 10: BN=128 tiles (halve A re-reads),
// templated <NK,NCBLK,NBLK>, term-major mma, 2 CTAs/SM
// ---------------------------------------------------------------------------

#define H 256
#define INTC 64
#define SBF_DIM 42
#define NRAD 6
#define BAS 8

#define MAXE 200704
#define MAXE_H ((size_t)MAXE * H)
#define MAXE_I ((size_t)MAXE * INTC)

__device__ float g_buf0[MAXE_H];
__device__ float g_buf1[MAXE_H];
__device__ float g_down[MAXE_I];
__device__ float g_agg[MAXE_I];
__device__ float g_Wr[NRAD * H];
__device__ __half g_P0h[MAXE_H], g_P0l[MAXE_H];
__device__ __half g_P1h[MAXE_H], g_P1l[MAXE_H];
__device__ __half g_P2h[MAXE_H], g_P2l[MAXE_H];
__device__ __half g_aggh[MAXE_I], g_aggl[MAXE_I];
__device__ __half g_Wsp[22 * 65536];

__device__ __forceinline__ float silu(float v) {
    return v / (1.0f + __expf(-v));
}
__device__ __forceinline__ void h_split(float v, __half& h, __half& l) {
    h = __float2half_rn(v);
    l = __float2half_rn(v - __half2float(h));
}

__device__ __forceinline__ void mma_f16(float* d, const uint32_t* a, const uint32_t* b) {
    asm volatile(
        "mma.sync.aligned.m16n8k16.row.col.f32.f16.f16.f32 "
        "{%0,%1,%2,%3},{%4,%5,%6,%7},{%8,%9},{%0,%1,%2,%3};\n"
        : "+f"(d[0]), "+f"(d[1]), "+f"(d[2]), "+f"(d[3])
        : "r"(a[0]), "r"(a[1]), "r"(a[2]), "r"(a[3]), "r"(b[0]), "r"(b[1]));
}
__device__ __forceinline__ void ldsm_x4(uint32_t* r, uint32_t addr) {
    asm volatile("ldmatrix.sync.aligned.m8n8.x4.shared.b16 {%0,%1,%2,%3}, [%4];"
                 : "=r"(r[0]), "=r"(r[1]), "=r"(r[2]), "=r"(r[3]) : "r"(addr));
}

__device__ __forceinline__ uint32_t smem_u32(const void* p) {
    uint32_t a;
    asm("{ .reg .u64 t; cvta.to.shared.u64 t, %1; cvt.u32.u64 %0, t; }" : "=r"(a) : "l"(p));
    return a;
}
__device__ __forceinline__ void cp_async16(uint32_t dst, const void* src, int szr) {
    asm volatile("cp.async.cg.shared.global [%0], [%1], 16, %2;"
                 :: "r"(dst), "l"(src), "r"(szr) : "memory");
}
#define CP_COMMIT() asm volatile("cp.async.commit_group;" ::: "memory")
#define CP_WAIT(n)  asm volatile("cp.async.wait_group %0;" :: "n"(n) : "memory")

// ---------------------------------------------------------------------------
// GEMM: BM=128, BN=32*NBLK, BK=16, 256 threads (8 warps: 4 rows x 2 cols),
// 4 stages. Stage: Ahi[0,6144) Alo[6144,12288) Bhi[12288,+B) Blo[+B,+2B)
// ---------------------------------------------------------------------------
#define BM 128
#define STAGES 4

template <int NK, int NCBLK, int NBLK>
__global__ void __launch_bounds__(256, 2) gemm_f16x2(
    const __half* __restrict__ Ah, const __half* __restrict__ Al,
    const __half* __restrict__ Bh, const __half* __restrict__ Bl,
    const float* __restrict__ bias, const float* __restrict__ mul,
    const float* __restrict__ addF,
    const __half* __restrict__ addH, const __half* __restrict__ addL,
    float* __restrict__ Cf, __half* __restrict__ Chi, __half* __restrict__ Clo,
    int M, int N) {

    constexpr int K    = NK * 16;
    constexpr int NT   = NBLK * 2;            // n-tiles (8 cols) per warp
    constexpr int BSTG = NBLK * 1024;         // B hi bytes per stage
    constexpr int STG  = 12288 + 2 * BSTG;    // stage stride
    constexpr int BN   = NBLK * 32;

    extern __shared__ char smem_raw[];
    char* bp = smem_raw;
    const uint32_t s0 = smem_u32(smem_raw);

    const int tid  = threadIdx.x;
    const int wid  = tid >> 5;
    const int lane = tid & 31;
    const int g    = lane >> 2;
    const int t    = lane & 3;
    const int wy   = wid >> 1;   // 0..3
    const int wx   = wid & 1;    // 0..1

    const int rowBase = blockIdx.x * BM;
    const int colBase = blockIdx.y * BN;
    const int cblk0   = colBase >> 5;

    // ---- hoisted cp.async addressing ----
    const int ar = tid >> 1, ac = tid & 1;
    const int gr = rowBase + ar;
    const bool aV = gr < M;
    const __half* aSrcH = Ah + (size_t)(aV ? gr : 0) * K + ac * 8;
    const __half* aSrcL = Al + (size_t)(aV ? gr : 0) * K + ac * 8;
    const uint32_t aDstH = s0 + (uint32_t)(ar * 48 + ac * 16);
    const uint32_t aDstL = aDstH + 6144u;
    constexpr int bStep = NCBLK * 512;        // halves per k-tile

    // B chunk mapping
    int bChunk;          // chunk index 0..(NBLK*64-1)
    const __half* bSrc0; // hi source base for this thread's chunk
    const __half* bSrc1; // lo source (or second chunk for NBLK=2 style)
    uint32_t bDst0, bDst1;
    if (NBLK == 4) {
        bChunk = tid;    // 256 chunks: every thread 1 hi + 1 lo
        const int cblkL = bChunk >> 6, rr = (bChunk >> 5) & 1, bln = bChunk & 31;
        const size_t off = ((size_t)((cblk0 + cblkL) * 2 + rr) * 32 + bln) * 8;
        bSrc0 = Bh + off;
        bSrc1 = Bl + off;
        bDst0 = s0 + 12288u + (uint32_t)bChunk * 16;
        bDst1 = bDst0 + (uint32_t)BSTG;
    } else {             // NBLK == 2: 128 chunks; tid<128 hi, tid>=128 lo
        bChunk = tid & 127;
        const int cblkL = bChunk >> 6, rr = (bChunk >> 5) & 1, bln = bChunk & 31;
        const size_t off = ((size_t)((cblk0 + cblkL) * 2 + rr) * 32 + bln) * 8;
        bSrc0 = ((tid < 128) ? Bh : Bl) + off;
        bSrc1 = nullptr;
        bDst0 = s0 + 12288u + (tid < 128 ? 0u : (uint32_t)BSTG) + (uint32_t)bChunk * 16;
        bDst1 = 0;
    }

    const uint32_t lds_a_off =
        (uint32_t)(((lane & 7) + ((lane >> 3) & 1) * 8) * 48 + ((lane >> 4) & 1) * 16);

    float acc[2][NT][4];
    #pragma unroll
    for (int i = 0; i < 2; i++)
        #pragma unroll
        for (int j = 0; j < NT; j++)
            #pragma unroll
            for (int r = 0; r < 4; r++) acc[i][j][r] = 0.f;

    #pragma unroll
    for (int s = 0; s < STAGES - 1; s++) {
        if (s < NK) {
            cp_async16(aDstH + s * STG, aSrcH + s * 16, aV ? 16 : 0);
            cp_async16(aDstL + s * STG, aSrcL + s * 16, aV ? 16 : 0);
            cp_async16(bDst0 + s * STG, bSrc0 + (size_t)s * bStep, 16);
            if (NBLK == 4)
                cp_async16(bDst1 + s * STG, bSrc1 + (size_t)s * bStep, 16);
        }
        CP_COMMIT();
    }

    #pragma unroll
    for (int it = 0; it < NK; ++it) {
        const int pend = NK - 1 - it;
        if (pend >= 2)      CP_WAIT(2);
        else if (pend == 1) CP_WAIT(1);
        else                CP_WAIT(0);
        __syncthreads();

        const int nx = it + STAGES - 1;
        if (nx < NK) {
            const uint32_t so = (uint32_t)(nx % STAGES) * STG;
            cp_async16(aDstH + so, aSrcH + nx * 16, aV ? 16 : 0);
            cp_async16(aDstL + so, aSrcL + nx * 16, aV ? 16 : 0);
            cp_async16(bDst0 + so, bSrc0 + (size_t)nx * bStep, 16);
            if (NBLK == 4)
                cp_async16(bDst1 + so, bSrc1 + (size_t)nx * bStep, 16);
            CP_COMMIT();
        }

        const uint32_t sb = (uint32_t)(it % STAGES) * STG;
        const uint32_t bHiBase = sb + 12288u;
        const uint32_t bLoBase = bHiBase + (uint32_t)BSTG;

        // ---- A fragments (ldmatrix) ----
        uint32_t ah[2][4], al[2][4];
        #pragma unroll
        for (int mt = 0; mt < 2; mt++) {
            const int m0 = wy * 32 + mt * 16;
            ldsm_x4(ah[mt], s0 + sb + (uint32_t)(m0 * 48) + lds_a_off);
            ldsm_x4(al[mt], s0 + sb + 6144u + (uint32_t)(m0 * 48) + lds_a_off);
        }

        // ---- B hi fragments ----
        uint32_t bh[NT][2];
        #pragma unroll
        for (int j = 0; j < NBLK / 2; j++) {
            const int cb = wx * (NBLK / 2) + j;
            uint4 v0 = *reinterpret_cast<uint4*>(bp + bHiBase + ((cb * 2 + 0) * 32 + lane) * 16);
            uint4 v1 = *reinterpret_cast<uint4*>(bp + bHiBase + ((cb * 2 + 1) * 32 + lane) * 16);
            bh[j * 4 + 0][0] = v0.x; bh[j * 4 + 1][0] = v0.y;
            bh[j * 4 + 2][0] = v0.z; bh[j * 4 + 3][0] = v0.w;
            bh[j * 4 + 0][1] = v1.x; bh[j * 4 + 1][1] = v1.y;
            bh[j * 4 + 2][1] = v1.z; bh[j * 4 + 3][1] = v1.w;
        }

        // term1: al * bh
        #pragma unroll
        for (int mt = 0; mt < 2; mt++)
            #pragma unroll
            for (int nt = 0; nt < NT; nt++)
                mma_f16(acc[mt][nt], al[mt], bh[nt]);

        // ---- B lo fragments ----
        uint32_t bl[NT][2];
        #pragma unroll
        for (int j = 0; j < NBLK / 2; j++) {
            const int cb = wx * (NBLK / 2) + j;
            uint4 v0 = *reinterpret_cast<uint4*>(bp + bLoBase + ((cb * 2 + 0) * 32 + lane) * 16);
            uint4 v1 = *reinterpret_cast<uint4*>(bp + bLoBase + ((cb * 2 + 1) * 32 + lane) * 16);
            bl[j * 4 + 0][0] = v0.x; bl[j * 4 + 1][0] = v0.y;
            bl[j * 4 + 2][0] = v0.z; bl[j * 4 + 3][0] = v0.w;
            bl[j * 4 + 0][1] = v1.x; bl[j * 4 + 1][1] = v1.y;
            bl[j * 4 + 2][1] = v1.z; bl[j * 4 + 3][1] = v1.w;
        }

        // term2: ah * bl
        #pragma unroll
        for (int mt = 0; mt < 2; mt++)
            #pragma unroll
            for (int nt = 0; nt < NT; nt++)
                mma_f16(acc[mt][nt], ah[mt], bl[nt]);

        // term3: ah * bh
        #pragma unroll
        for (int mt = 0; mt < 2; mt++)
            #pragma unroll
            for (int nt = 0; nt < NT; nt++)
                mma_f16(acc[mt][nt], ah[mt], bh[nt]);
    }

    // epilogue
    #pragma unroll
    for (int mt = 0; mt < 2; mt++) {
        #pragma unroll
        for (int nt = 0; nt < NT; nt++) {
            const int c0 = colBase + wx * (NT * 8) + nt * 8 + 2 * t;
            if (c0 >= N) continue;
            #pragma unroll
            for (int half = 0; half < 2; half++) {
                const int row = rowBase + wy * 32 + mt * 16 + g + 8 * half;
                if (row >= M) continue;
                const size_t idx = (size_t)row * N + c0;
                float v0 = acc[mt][nt][half * 2];
                float v1 = acc[mt][nt][half * 2 + 1];
                if (bias) { v0 += bias[c0]; v1 += bias[c0 + 1]; }
                v0 = silu(v0); v1 = silu(v1);
                if (mul)  { v0 *= mul[idx];  v1 *= mul[idx + 1]; }
                if (addF) { v0 += addF[idx]; v1 += addF[idx + 1]; }
                if (addH) {
                    v0 += __half2float(addH[idx]) + __half2float(addL[idx]);
                    v1 += __half2float(addH[idx + 1]) + __half2float(addL[idx + 1]);
                }
                if (Cf) { Cf[idx] = v0; Cf[idx + 1] = v1; }
                if (Chi) {
                    __half h0, l0, h1, l1;
                    h_split(v0, h0, l0); h_split(v1, h1, l1);
                    *reinterpret_cast<__half2*>(Chi + idx) = __halves2half2(h0, h1);
                    *reinterpret_cast<__half2*>(Clo + idx) = __halves2half2(l0, l1);
                }
            }
        }
    }
}

// ---------------------------------------------------------------------------
// Prep kernels
// ---------------------------------------------------------------------------
__global__ void split_w_kernel(
    const float* p0, const float* p1, const float* p2, const float* p3,
    const float* p4, const float* p5, const float* p6, const float* p7,
    const float* p8, const float* p9, const float* p10) {
    const float* srcs[11] = {p0, p1, p2, p3, p4, p5, p6, p7, p8, p9, p10};
    const int KK[11]  = {256, 256, 256, 64, 256, 256, 256, 256, 256, 256, 256};
    const int NN[11]  = {256, 256, 64, 256, 256, 256, 256, 256, 256, 256, 256};
    const int NC[11]  = {8, 8, 4, 8, 8, 8, 8, 8, 8, 8, 8};
    const int w = blockIdx.y;
    const int i = blockIdx.x * 256 + threadIdx.x;
    const int K = KK[w], N = NN[w], ncblk = NC[w];
    const int total = (K / 16) * ncblk * 256;
    if (i >= total) return;
    const int kb = i / (ncblk * 256);
    const int rem = i % (ncblk * 256);
    const int cblk = rem >> 8;
    const int j = rem & 255;
    const int r = j >> 7, lane = (j >> 2) & 31, nt = j & 3;
    const int gg = lane >> 2, tt = lane & 3;
    const int k0 = kb * 16 + r * 8 + tt * 2;
    const int n  = cblk * 32 + nt * 8 + gg;
    const float* W = srcs[w];
    float v0 = (n < N && k0 < K)     ? W[(size_t)k0 * N + n]       : 0.f;
    float v1 = (n < N && k0 + 1 < K) ? W[(size_t)(k0 + 1) * N + n] : 0.f;
    __half h0, l0, h1, l1;
    h_split(v0, h0, l0); h_split(v1, h1, l1);
    const size_t o = (size_t)i * 2;
    __half* hi = g_Wsp + (size_t)(2 * w) * 65536;
    __half* lo = g_Wsp + (size_t)(2 * w + 1) * 65536;
    *reinterpret_cast<__half2*>(hi + o) = __halves2half2(h0, h1);
    *reinterpret_cast<__half2*>(lo + o) = __halves2half2(l0, l1);
}

__global__ void split_pair_kernel(const float* __restrict__ src,
                                  __half* __restrict__ hi, __half* __restrict__ lo,
                                  int n4) {
    int i = blockIdx.x * 256 + threadIdx.x;
    if (i < n4) {
        float4 v = reinterpret_cast<const float4*>(src)[i];
        __half h0, l0, h1, l1, h2, l2, h3, l3;
        h_split(v.x, h0, l0); h_split(v.y, h1, l1);
        h_split(v.z, h2, l2); h_split(v.w, h3, l3);
        reinterpret_cast<__half2*>(hi)[i * 2]     = __halves2half2(h0, h1);
        reinterpret_cast<__half2*>(hi)[i * 2 + 1] = __halves2half2(h2, h3);
        reinterpret_cast<__half2*>(lo)[i * 2]     = __halves2half2(l0, l1);
        reinterpret_cast<__half2*>(lo)[i * 2 + 1] = __halves2half2(l2, l3);
    }
}

__global__ void zero_agg_kernel(int n4) {
    int i = blockIdx.x * 256 + threadIdx.x;
    if (i < n4) reinterpret_cast<float4*>(g_agg)[i] = make_float4(0.f, 0.f, 0.f, 0.f);
}

__global__ void wr_kernel(const float* __restrict__ W1, const float* __restrict__ W2) {
    int c = threadIdx.x;
    #pragma unroll
    for (int k = 0; k < NRAD; k++) {
        float v = 0.f;
        #pragma unroll
        for (int j = 0; j < BAS; j++) v += W1[k * BAS + j] * W2[j * H + c];
        g_Wr[k * H + c] = v;
    }
}

__global__ void __launch_bounds__(256) rbfe_kernel(
    const float* __restrict__ rbf, float* __restrict__ out, int E) {
    __shared__ float srbf[64 * NRAD];
    const int tid = threadIdx.x;
    const int e0 = blockIdx.x * 64;
    float w[NRAD];
    #pragma unroll
    for (int k = 0; k < NRAD; k++) w[k] = g_Wr[k * H + tid];
    for (int i = tid; i < 64 * NRAD; i += 256) {
        int e = e0 + i / NRAD;
        srbf[i] = (e < E) ? rbf[(size_t)e * NRAD + (i % NRAD)] : 0.f;
    }
    __syncthreads();
    for (int r = 0; r < 64; r++) {
        int e = e0 + r;
        if (e >= E) break;
        float v = 0.f;
        #pragma unroll
        for (int k = 0; k < NRAD; k++) v += w[k] * srbf[r * NRAD + k];
        out[(size_t)e * H + tid] = v;
    }
}

// ---------------------------------------------------------------------------
// Triplet scatter (red.global.add.v4)
// ---------------------------------------------------------------------------
#define SC_TRI 32
__global__ void __launch_bounds__(512) scatter_v4_kernel(
    const float* __restrict__ sbf, const int* __restrict__ idx_kj,
    const int* __restrict__ idx_ji, const float* __restrict__ W1,
    const float* __restrict__ W2, int T) {
    __shared__ float W1s[SBF_DIM * BAS];
    __shared__ float W2s[BAS * INTC];
    __shared__ float sbfs[SC_TRI][SBF_DIM + 2];
    __shared__ float bs[SC_TRI][BAS];

    const int tid = threadIdx.x;
    for (int i = tid; i < SBF_DIM * BAS; i += 512) W1s[i] = W1[i];
    for (int i = tid; i < BAS * INTC; i += 512) W2s[i] = W2[i];

    const int t = tid >> 4;
    const int l = tid & 15;
    const long tri = (long)blockIdx.x * SC_TRI + t;
    const bool valid = tri < (long)T;

    if (valid) {
        #pragma unroll
        for (int i = l; i < SBF_DIM; i += 16) sbfs[t][i] = sbf[tri * SBF_DIM + i];
    }
    __syncthreads();

    if (valid && l < BAS) {
        float b = 0.f;
        #pragma unroll
        for (int j = 0; j < SBF_DIM; j++) b += sbfs[t][j] * W1s[j * BAS + l];
        bs[t][l] = b;
    }
    __syncthreads();

    if (valid) {
        const int c0 = l * 4;
        float s0 = 0.f, s1 = 0.f, s2 = 0.f, s3 = 0.f;
        #pragma unroll
        for (int k = 0; k < BAS; k++) {
            const float bk = bs[t][k];
            const float* w = &W2s[k * INTC + c0];
            s0 += bk * w[0]; s1 += bk * w[1]; s2 += bk * w[2]; s3 += bk * w[3];
        }
        const int kj = idx_kj[tri];
        const int ji = idx_ji[tri];
        const float4 d = __ldg(reinterpret_cast<const float4*>(&g_down[(size_t)kj * INTC + c0]));
        s0 *= d.x; s1 *= d.y; s2 *= d.z; s3 *= d.w;
        float* dst = &g_agg[(size_t)ji * INTC + c0];
        asm volatile("red.global.add.v4.f32 [%0], {%1,%2,%3,%4};"
                     :: "l"(dst), "f"(s0), "f"(s1), "f"(s2), "f"(s3) : "memory");
    }
}

// ---------------------------------------------------------------------------
// Host orchestration
// ---------------------------------------------------------------------------
struct Pair { __half* h; __half* l; };

#define SMEM_BIG  (4 * (12288 + 2 * 4096))   // 81920  (NBLK=4)
#define SMEM_SML  (4 * (12288 + 2 * 2048))   // 65536  (NBLK=2)

static inline void launch_gemm(Pair A, const __half* bh, const __half* bl,
                               const float* bias, const float* mul, const float* addF,
                               Pair addP, float* Cf, Pair Cp,
                               int M, int N, int K, int ncblk) {
    if (K == 256 && N == 256) {
        dim3 grid((M + BM - 1) / BM, 2);
        gemm_f16x2<16, 8, 4><<<grid, 256, SMEM_BIG>>>(A.h, A.l, bh, bl, bias, mul, addF,
                                                      addP.h, addP.l, Cf, Cp.h, Cp.l, M, N);
    } else if (K == 256) {   // N = 64
        dim3 grid((M + BM - 1) / BM, 1);
        gemm_f16x2<16, 4, 2><<<grid, 256, SMEM_SML>>>(A.h, A.l, bh, bl, bias, mul, addF,
                                                      addP.h, addP.l, Cf, Cp.h, Cp.l, M, N);
    } else {                 // K = 64, N = 256
        dim3 grid((M + BM - 1) / BM, 2);
        gemm_f16x2<4, 8, 4><<<grid, 256, SMEM_BIG>>>(A.h, A.l, bh, bl, bias, mul, addF,
                                                     addP.h, addP.l, Cf, Cp.h, Cp.l, M, N);
    }
}

extern "C" void kernel_launch(void* const* d_in, const int* in_sizes, int n_in,
                              void* d_out, int out_size) {
    const float* x      = (const float*)d_in[0];
    const float* rbf    = (const float*)d_in[1];
    const float* sbf    = (const float*)d_in[2];
    const int*   idx_kj = (const int*)d_in[3];
    const int*   idx_ji = (const int*)d_in[4];
    const float* W_rbf1 = (const float*)d_in[5];
    const float* W_rbf2 = (const float*)d_in[6];
    const float* W_sbf1 = (const float*)d_in[7];
    const float* W_sbf2 = (const float*)d_in[8];
    const float* W_kj   = (const float*)d_in[9];
    const float* b_kj   = (const float*)d_in[10];
    const float* W_ji   = (const float*)d_in[11];
    const float* b_ji   = (const float*)d_in[12];
    const float* W_down = (const float*)d_in[13];
    const float* W_up   = (const float*)d_in[14];
    const float* rb_W1  = (const float*)d_in[15];
    const float* rb_b1  = (const float*)d_in[16];
    const float* rb_W2  = (const float*)d_in[17];
    const float* rb_b2  = (const float*)d_in[18];
    const float* W_lin  = (const float*)d_in[19];
    const float* b_lin  = (const float*)d_in[20];
    const float* ra_W1  = (const float*)d_in[21];
    const float* ra_b1  = (const float*)d_in[22];
    const float* ra_W2  = (const float*)d_in[23];
    const float* ra_b2  = (const float*)d_in[24];

    const int E = in_sizes[0] / H;
    const int T = in_sizes[3];
    float* out = (float*)d_out;

    cudaFuncSetAttribute((const void*)gemm_f16x2<16, 8, 4>,
                         cudaFuncAttributeMaxDynamicSharedMemorySize, SMEM_BIG);
    cudaFuncSetAttribute((const void*)gemm_f16x2<16, 4, 2>,
                         cudaFuncAttributeMaxDynamicSharedMemorySize, SMEM_SML);
    cudaFuncSetAttribute((const void*)gemm_f16x2<4, 8, 4>,
                         cudaFuncAttributeMaxDynamicSharedMemorySize, SMEM_BIG);

    float *buf0, *buf1, *down, *agg;
    __half *P0h, *P0l, *P1h, *P1l, *P2h, *P2l, *aggh, *aggl, *wsp;
    cudaGetSymbolAddress((void**)&buf0, g_buf0);
    cudaGetSymbolAddress((void**)&buf1, g_buf1);
    cudaGetSymbolAddress((void**)&down, g_down);
    cudaGetSymbolAddress((void**)&agg,  g_agg);
    cudaGetSymbolAddress((void**)&P0h, g_P0h); cudaGetSymbolAddress((void**)&P0l, g_P0l);
    cudaGetSymbolAddress((void**)&P1h, g_P1h); cudaGetSymbolAddress((void**)&P1l, g_P1l);
    cudaGetSymbolAddress((void**)&P2h, g_P2h); cudaGetSymbolAddress((void**)&P2l, g_P2l);
    cudaGetSymbolAddress((void**)&aggh, g_aggh); cudaGetSymbolAddress((void**)&aggl, g_aggl);
    cudaGetSymbolAddress((void**)&wsp, g_Wsp);
    #define WHI(w) (wsp + (size_t)(2 * (w)) * 65536)
    #define WLO(w) (wsp + (size_t)(2 * (w) + 1) * 65536)

    const Pair P0{P0h, P0l}, P1{P1h, P1l}, P2{P2h, P2l}, Pagg{aggh, aggl};
    const Pair NOP{nullptr, nullptr};

    split_w_kernel<<<dim3(128, 11), 256>>>(
        W_ji, W_kj, W_down, W_up, rb_W1, rb_W2, W_lin, ra_W1, ra_W2,
        ra_W1 + (size_t)H * H, ra_W2 + (size_t)H * H);
    wr_kernel<<<1, 256>>>(W_rbf1, W_rbf2);
    split_pair_kernel<<<((E * H / 4) + 255) / 256, 256>>>(x, P0h, P0l, E * H / 4);

    // L4: big GEMM (ncu slot)
    launch_gemm(P0, WHI(0), WLO(0), b_ji, nullptr, nullptr, NOP, buf0, NOP, E, H, H, 8);
    rbfe_kernel<<<(E + 63) / 64, 256>>>(rbf, buf1, E);
    zero_agg_kernel<<<(E * INTC / 4 + 255) / 256, 256>>>(E * INTC / 4);
    launch_gemm(P0, WHI(1), WLO(1), b_kj, buf1, nullptr, NOP, nullptr, P1, E, H, H, 8);
    launch_gemm(P1, WHI(2), WLO(2), nullptr, nullptr, nullptr, NOP, down, NOP, E, INTC, H, 4);

    scatter_v4_kernel<<<(T + SC_TRI - 1) / SC_TRI, 512>>>(sbf, idx_kj, idx_ji,
                                                          W_sbf1, W_sbf2, T);
    split_pair_kernel<<<((E * INTC / 4) + 255) / 256, 256>>>(agg, aggh, aggl, E * INTC / 4);

    launch_gemm(Pagg, WHI(3), WLO(3), nullptr, nullptr, buf0, NOP, nullptr, P2, E, H, INTC, 8);
    launch_gemm(P2, WHI(4), WLO(4), rb_b1, nullptr, nullptr, NOP, nullptr, P1, E, H, H, 8);
    launch_gemm(P1, WHI(5), WLO(5), rb_b2, nullptr, nullptr, P2, nullptr, P0, E, H, H, 8);
    launch_gemm(P0, WHI(6), WLO(6), b_lin, nullptr, x, NOP, nullptr, P2, E, H, H, 8);
    launch_gemm(P2, WHI(7), WLO(7), ra_b1, nullptr, nullptr, NOP, nullptr, P1, E, H, H, 8);
    launch_gemm(P1, WHI(8), WLO(8), ra_b2, nullptr, nullptr, P2, nullptr, P0, E, H, H, 8);
    launch_gemm(P0, WHI(9), WLO(9), ra_b1 + H, nullptr, nullptr, NOP, nullptr, P1, E, H, H, 8);
    launch_gemm(P1, WHI(10), WLO(10), ra_b2 + H, nullptr, nullptr, P0, out, NOP, E, H, H, 8);
}